// round 11
// baseline (speedup 1.0000x reference)
#include <cuda_runtime.h>
#include <cuda_bf16.h>
#include <stdint.h>
#include <math.h>

#define BATCH 2048
#define NTOK 98
#define DIM 128
#define HEADS 4
#define NWIN 256
#define NN (NTOK * NTOK)   // 9604
#define MTOT (BATCH * NTOK)  // 200704

// Scratch (device globals)
__device__ float g_qkv[(size_t)MTOT * 384];                 // [m][s*128+h*32+d]
__device__ float g_att[(size_t)MTOT * 128];                 // [m][h*32+d]
__device__ __nv_bfloat16 g_sbm[(size_t)NWIN * HEADS * NN];  // bias+mask bf16
__device__ uint4 g_wfrag[16384];                            // W in MMA-fragment layout

// ===========================================================================
__device__ __forceinline__ uint32_t smem_u32(const void* p) {
    uint32_t a;
    asm("{ .reg .u64 t; cvta.to.shared.u64 t, %1; cvt.u32.u64 %0, t; }" : "=r"(a) : "l"(p));
    return a;
}
__device__ __forceinline__ void ldsm_x4(uint32_t* r, uint32_t addr) {
    asm volatile("ldmatrix.sync.aligned.m8n8.x4.shared.b16 {%0,%1,%2,%3}, [%4];"
                 : "=r"(r[0]), "=r"(r[1]), "=r"(r[2]), "=r"(r[3]) : "r"(addr));
}
__device__ __forceinline__ void ldsm_x2(uint32_t* r, uint32_t addr) {
    asm volatile("ldmatrix.sync.aligned.m8n8.x2.shared.b16 {%0,%1}, [%2];"
                 : "=r"(r[0]), "=r"(r[1]) : "r"(addr));
}
__device__ __forceinline__ void ldsm_x4t(uint32_t* r, uint32_t addr) {
    asm volatile("ldmatrix.sync.aligned.m8n8.x4.trans.shared.b16 {%0,%1,%2,%3}, [%4];"
                 : "=r"(r[0]), "=r"(r[1]), "=r"(r[2]), "=r"(r[3]) : "r"(addr));
}
__device__ __forceinline__ void mma_bf16(float* d, const uint32_t* a, const uint32_t* b) {
    asm volatile("mma.sync.aligned.m16n8k16.row.col.f32.bf16.bf16.f32 "
                 "{%0,%1,%2,%3}, {%4,%5,%6,%7}, {%8,%9}, {%0,%1,%2,%3};"
                 : "+f"(d[0]), "+f"(d[1]), "+f"(d[2]), "+f"(d[3])
                 : "r"(a[0]), "r"(a[1]), "r"(a[2]), "r"(a[3]), "r"(b[0]), "r"(b[1]));
}
__device__ __forceinline__ uint32_t packbf(float a, float b) {
    __nv_bfloat162 t = __float22bfloat162_rn(make_float2(a, b));
    return *(uint32_t*)&t;
}
__device__ __forceinline__ float lopart(float v) {
    return v - __bfloat162float(__float2bfloat16(v));
}
__device__ __forceinline__ void split4(float4 v, uint2& hi, uint2& lo) {
    __nv_bfloat16 hx = __float2bfloat16(v.x), hy = __float2bfloat16(v.y);
    __nv_bfloat16 hz = __float2bfloat16(v.z), hw = __float2bfloat16(v.w);
    __nv_bfloat162 h0 = __halves2bfloat162(hx, hy), h1 = __halves2bfloat162(hz, hw);
    hi.x = *(uint32_t*)&h0; hi.y = *(uint32_t*)&h1;
    lo.x = packbf(v.x - __bfloat162float(hx), v.y - __bfloat162float(hy));
    lo.y = packbf(v.z - __bfloat162float(hz), v.w - __bfloat162float(hw));
}
// swizzled smem address: 256B-pitch rows, XOR 16B-chunk by row&7
__device__ __forceinline__ uint32_t swz(uint32_t r, uint32_t cb) {
    return (r << 8) + (cb ^ ((r & 7) << 4));
}

// ===========================================================================
// bias+mask combine
// ===========================================================================
__global__ void build_sbm_kernel(const float* __restrict__ table,
                                 const int* __restrict__ rel,
                                 const float* __restrict__ mask) {
    int nm = blockIdx.x * 256 + threadIdx.x;
    int wh = blockIdx.y;
    if (nm < NN) {
        int w = wh >> 2, h = wh & 3;
        float v = table[rel[nm] * HEADS + h] + mask[(size_t)w * NN + nm];
        g_sbm[(size_t)wh * NN + nm] = __float2bfloat16(v);
    }
}

// ===========================================================================
// W pre-split into MMA B-fragment layout.
// ===========================================================================
__global__ void split_w_kernel(const float* __restrict__ qkv_w,
                               const float* __restrict__ proj_w) {
    int idx = blockIdx.x * 256 + threadIdx.x;   // 16384
    int tile = idx >> 12;
    int rem = idx & 4095;
    int lane = rem & 31;
    int nblk = (rem >> 5) & 15;
    int kc = rem >> 9;
    int n = nblk * 8 + (lane >> 2);
    int k0 = kc * 16 + (lane & 3) * 2;
    const float* W = (tile < 3) ? qkv_w + (size_t)(tile * 128 + n) * 128
                                : proj_w + (size_t)n * 128;
    float2 a = *(const float2*)(W + k0);
    float2 b = *(const float2*)(W + k0 + 8);
    uint4 o;
    {
        __nv_bfloat162 h = __halves2bfloat162(__float2bfloat16(a.x), __float2bfloat16(a.y));
        o.x = *(uint32_t*)&h;
        __nv_bfloat162 h2 = __halves2bfloat162(__float2bfloat16(b.x), __float2bfloat16(b.y));
        o.y = *(uint32_t*)&h2;
    }
    o.z = packbf(lopart(a.x), lopart(a.y));
    o.w = packbf(lopart(b.x), lopart(b.y));
    g_wfrag[idx] = o;
}

// ===========================================================================
// HMMA GEMM (unchanged from R9): 64M x NITER*128N, W frags from L2.
// ===========================================================================
template<int NITER>
__global__ __launch_bounds__(256, 3) void gemm_hmma(
    const float* __restrict__ Af, const uint4* __restrict__ Wfrag,
    const float* __restrict__ bias, float* __restrict__ Cf)
{
    __shared__ char sm[32768];
    const uint32_t smb = smem_u32(sm);
    const int tid = threadIdx.x;
    const int wid = tid >> 5, lane = tid & 31;
    const size_t m0 = (size_t)blockIdx.x * 64;
    const int N = NITER * 128;

#pragma unroll
    for (int i = 0; i < 8; i++) {
        int idx = tid + 256 * i;
        int r = idx >> 5;
        int c4 = (idx & 31) << 2;
        float4 v = *(const float4*)(Af + (m0 + r) * 128 + c4);
        uint2 hi, lo;
        split4(v, hi, lo);
        *(uint2*)(sm + swz(r, c4 * 2)) = hi;
        *(uint2*)(sm + 16384 + swz(r, c4 * 2)) = lo;
    }
    __syncthreads();

    const int wm = (wid & 1) * 32;
    const int wnb = (wid >> 1) * 4;
    const int rq = lane >> 2, cq = (lane & 3) * 2;

#pragma unroll 1
    for (int it = 0; it < NITER; it++) {
        const int n0 = it * 128;

        float acc[2][4][4];
#pragma unroll
        for (int mi = 0; mi < 2; mi++)
#pragma unroll
            for (int ni = 0; ni < 4; ni++)
#pragma unroll
                for (int c = 0; c < 4; c++) acc[mi][ni][c] = 0.f;

#pragma unroll
        for (int kc = 0; kc < 8; kc++) {
            uint32_t cb = (uint32_t)(kc * 32 + ((lane >> 4) & 1) * 16);
            uint32_t ah[2][4], al[2][4];
#pragma unroll
            for (int mi = 0; mi < 2; mi++) {
                uint32_t r = (uint32_t)(wm + mi * 16 + (lane & 15));
                ldsm_x4(ah[mi], smb + swz(r, cb));
                ldsm_x4(al[mi], smb + 16384 + swz(r, cb));
            }
            const uint4* wp = Wfrag + ((size_t)(it * 8 + kc) * 16 + wnb) * 32 + lane;
#pragma unroll
            for (int ni = 0; ni < 4; ni++) {
                uint4 w = wp[ni * 32];
                uint32_t B0[2] = {w.x, w.y};
                uint32_t Bl[2] = {w.z, w.w};
#pragma unroll
                for (int mi = 0; mi < 2; mi++) {
                    mma_bf16(acc[mi][ni], ah[mi], B0);
                    mma_bf16(acc[mi][ni], al[mi], B0);
                    mma_bf16(acc[mi][ni], ah[mi], Bl);
                }
            }
        }

#pragma unroll
        for (int mi = 0; mi < 2; mi++) {
            size_t rA = m0 + wm + mi * 16 + rq;
            size_t rB = rA + 8;
#pragma unroll
            for (int ni = 0; ni < 4; ni++) {
                int col = n0 + wnb * 8 + ni * 8 + cq;
                float b0 = bias[col], b1 = bias[col + 1];
                *(float2*)(Cf + rA * N + col) =
                    make_float2(acc[mi][ni][0] + b0, acc[mi][ni][1] + b1);
                *(float2*)(Cf + rB * N + col) =
                    make_float2(acc[mi][ni][2] + b0, acc[mi][ni][3] + b1);
            }
        }
    }
}

// ===========================================================================
// HMMA attention: one CTA per (window, head), 256 threads (8 warps x 16 rows).
// B-side fragments loaded via x4 ldmatrix (2 blocks per instruction).
// ===========================================================================
#define PITCH 80
#define QH_OFF 0
#define QL_OFF 10240
#define KH_OFF 20480
#define KL_OFF 29440
#define VH_OFF 38400
#define VL_OFF 47360
#define ATTN_SMEM 56320

__global__ __launch_bounds__(256, 3) void attn_hmma_kernel() {
    extern __shared__ char smraw[];
    const uint32_t smb = smem_u32(smraw);
    char* sm = smraw;

    const int b = blockIdx.x, h = blockIdx.y;
    const int tid = threadIdx.x;
    const int wid = tid >> 5, lane = tid & 31;

    // ---- zero only pad rows (98..111) of all 6 tiles ----
    {
        uint4 z = make_uint4(0, 0, 0, 0);
        for (int idx = tid; idx < 420; idx += 256) {
            int t = idx / 70;
            int rem = idx - t * 70;
            int row = 98 + rem / 5;
            int ch = rem % 5;
            uint32_t base = (t < 2) ? (uint32_t)(t * 10240)
                                    : (uint32_t)(20480 + (t - 2) * 8960);
            *(uint4*)(sm + base + row * PITCH + ch * 16) = z;
        }
    }
    __syncthreads();

    // ---- load Q (scaled) / K / V, split hi/lo bf16, pitch-80 rows ----
    const float scale = 0.17677669529663687f;
    const float* qg = g_qkv + ((size_t)b * NTOK) * 384 + h * 32;
    for (int idx = tid; idx < NTOK * 8; idx += 256) {
        int n = idx >> 3, c4 = (idx & 7) << 2;
        const float* src = qg + (size_t)n * 384 + c4;
        uint32_t off = (uint32_t)(n * PITCH + c4 * 2);
        uint2 hi, lo;

        float4 q = *(const float4*)src;
        q.x *= scale; q.y *= scale; q.z *= scale; q.w *= scale;
        split4(q, hi, lo);
        *(uint2*)(sm + QH_OFF + off) = hi;
        *(uint2*)(sm + QL_OFF + off) = lo;

        split4(*(const float4*)(src + 128), hi, lo);
        *(uint2*)(sm + KH_OFF + off) = hi;
        *(uint2*)(sm + KL_OFF + off) = lo;

        split4(*(const float4*)(src + 256), hi, lo);
        *(uint2*)(sm + VH_OFF + off) = hi;
        *(uint2*)(sm + VL_OFF + off) = lo;
    }
    __syncthreads();

    if (wid == 7) return;   // rows 112..127 are pure padding

    const int l8 = lane & 7;
    const int rq = lane >> 2;
    const int cq = (lane & 3) * 2;
    const int sel16 = (lane >> 4) & 1;     // 0 for lanes 0-15, 1 for 16-31

    // ---- S = QK^T, 3 passes; warp owns rows [16*wid, 16*wid+16) ----
    float acc[13][4];
#pragma unroll
    for (int nt = 0; nt < 13; nt++)
#pragma unroll
        for (int c = 0; c < 4; c++) acc[nt][c] = 0.f;

    uint32_t qbase[3] = {smb + QH_OFF, smb + QH_OFF, smb + QL_OFF};
    uint32_t kbase[3] = {smb + KH_OFF, smb + KL_OFF, smb + KH_OFF};

#pragma unroll 1
    for (int p = 0; p < 3; p++) {
        uint32_t qb = qbase[p], kb = kbase[p];
#pragma unroll
        for (int kc = 0; kc < 2; kc++) {
            uint32_t r = (uint32_t)(wid * 16 + (lane & 15));
            uint32_t aoff = (uint32_t)(kc * 32 + sel16 * 16);
            uint32_t a[4];
            ldsm_x4(a, qb + r * PITCH + aoff);
            uint32_t boff = (uint32_t)(kc * 32 + ((lane >> 3) & 1) * 16);
            // 6 paired nt via x4 (lanes 16-31 address the odd nt block)
#pragma unroll
            for (int nt2 = 0; nt2 < 6; nt2++) {
                uint32_t bf[4];
                uint32_t row = (uint32_t)((2 * nt2 + sel16) * 8 + l8);
                ldsm_x4(bf, kb + row * PITCH + boff);
                mma_bf16(acc[2 * nt2], a, bf);
                mma_bf16(acc[2 * nt2 + 1], a, bf + 2);
            }
            // tail nt = 12
            {
                uint32_t bf[2];
                ldsm_x2(bf, kb + (uint32_t)(96 + l8) * PITCH + boff);
                mma_bf16(acc[12], a, bf);
            }
        }
    }

    // ---- bias+mask add (direct from gmem), softmax ----
    const __nv_bfloat16* sbm = g_sbm + ((size_t)((b & (NWIN - 1)) * HEADS + h)) * NN;
    const int rA = wid * 16 + rq;
    const int rB = rA + 8;
    float mxA = -1e30f, mxB = -1e30f;
#pragma unroll
    for (int nt = 0; nt < 13; nt++) {
        int col = nt * 8 + cq;
        if (col < 98) {
            if (rA < 98) {
                uint32_t u = __ldg((const uint32_t*)(sbm + rA * 98 + col));
                __nv_bfloat162 bb = *(__nv_bfloat162*)&u;
                acc[nt][0] += __bfloat162float(bb.x);
                acc[nt][1] += __bfloat162float(bb.y);
            }
            if (rB < 98) {
                uint32_t u = __ldg((const uint32_t*)(sbm + rB * 98 + col));
                __nv_bfloat162 bb = *(__nv_bfloat162*)&u;
                acc[nt][2] += __bfloat162float(bb.x);
                acc[nt][3] += __bfloat162float(bb.y);
            }
        } else {
            acc[nt][0] = -1e30f; acc[nt][1] = -1e30f;
            acc[nt][2] = -1e30f; acc[nt][3] = -1e30f;
        }
        mxA = fmaxf(mxA, fmaxf(acc[nt][0], acc[nt][1]));
        mxB = fmaxf(mxB, fmaxf(acc[nt][2], acc[nt][3]));
    }
    mxA = fmaxf(mxA, __shfl_xor_sync(0xffffffffu, mxA, 1));
    mxA = fmaxf(mxA, __shfl_xor_sync(0xffffffffu, mxA, 2));
    mxB = fmaxf(mxB, __shfl_xor_sync(0xffffffffu, mxB, 1));
    mxB = fmaxf(mxB, __shfl_xor_sync(0xffffffffu, mxB, 2));
    float sA = 0.f, sB = 0.f;
#pragma unroll
    for (int nt = 0; nt < 13; nt++) {
        float e0 = __expf(acc[nt][0] - mxA);
        float e1 = __expf(acc[nt][1] - mxA);
        float e2 = __expf(acc[nt][2] - mxB);
        float e3 = __expf(acc[nt][3] - mxB);
        acc[nt][0] = e0; acc[nt][1] = e1;
        acc[nt][2] = e2; acc[nt][3] = e3;
        sA += e0 + e1; sB += e2 + e3;
    }
    sA += __shfl_xor_sync(0xffffffffu, sA, 1);
    sA += __shfl_xor_sync(0xffffffffu, sA, 2);
    sB += __shfl_xor_sync(0xffffffffu, sB, 1);
    sB += __shfl_xor_sync(0xffffffffu, sB, 2);

    // ---- O = P V, 3 passes; V frags via x4.trans (2 nh per instruction) ----
    float oacc[4][4];
#pragma unroll
    for (int nh = 0; nh < 4; nh++)
#pragma unroll
        for (int c = 0; c < 4; c++) oacc[nh][c] = 0.f;

    uint32_t vbase[3] = {smb + VH_OFF, smb + VL_OFF, smb + VH_OFF};

#pragma unroll 1
    for (int p = 0; p < 3; p++) {
        uint32_t vb = vbase[p];
        bool lo = (p == 2);
#pragma unroll
        for (int kc = 0; kc < 7; kc++) {
            int nt0 = 2 * kc, nt1 = nt0 + 1;
            float v0 = acc[nt0][0], v1 = acc[nt0][1];
            float v2 = acc[nt0][2], v3 = acc[nt0][3];
            float w0 = 0.f, w1 = 0.f, w2 = 0.f, w3 = 0.f;
            if (nt1 < 13) {
                w0 = acc[nt1][0]; w1 = acc[nt1][1];
                w2 = acc[nt1][2]; w3 = acc[nt1][3];
            }
            if (lo) {
                v0 = lopart(v0); v1 = lopart(v1); v2 = lopart(v2); v3 = lopart(v3);
                w0 = lopart(w0); w1 = lopart(w1); w2 = lopart(w2); w3 = lopart(w3);
            }
            uint32_t amat[4];
            amat[0] = packbf(v0, v1);
            amat[1] = packbf(v2, v3);
            amat[2] = packbf(w0, w1);
            amat[3] = packbf(w2, w3);
            uint32_t vrow = (uint32_t)(kc * 16 + ((lane >> 3) & 1) * 8 + l8);
#pragma unroll
            for (int nh2 = 0; nh2 < 2; nh2++) {
                uint32_t bf[4];
                ldsm_x4t(bf, vb + vrow * PITCH + (uint32_t)((2 * nh2 + sel16) * 16));
                mma_bf16(oacc[2 * nh2], amat, bf);
                mma_bf16(oacc[2 * nh2 + 1], amat, bf + 2);
            }
        }
    }

    // ---- epilogue ----
    float invA = 1.0f / sA;
    float invB = 1.0f / sB;
#pragma unroll
    for (int nh = 0; nh < 4; nh++) {
        int col = nh * 8 + cq;
        if (rA < 98) {
            float2 o = make_float2(oacc[nh][0] * invA, oacc[nh][1] * invA);
            *(float2*)(g_att + ((size_t)b * NTOK + rA) * 128 + h * 32 + col) = o;
        }
        if (rB < 98) {
            float2 o = make_float2(oacc[nh][2] * invB, oacc[nh][3] * invB);
            *(float2*)(g_att + ((size_t)b * NTOK + rB) * 128 + h * 32 + col) = o;
        }
    }
}

// ===========================================================================
extern "C" void kernel_launch(void* const* d_in, const int* in_sizes, int n_in,
                              void* d_out, int out_size) {
    const float* x          = (const float*)d_in[0];
    const float* mask       = (const float*)d_in[1];
    const float* qkv_w      = (const float*)d_in[2];
    const float* qkv_b      = (const float*)d_in[3];
    const float* proj_w     = (const float*)d_in[4];
    const float* proj_b     = (const float*)d_in[5];
    const float* bias_table = (const float*)d_in[6];
    const int*   rel_index  = (const int*)d_in[7];
    float* out = (float*)d_out;

    void *qkv_ptr, *att_ptr, *wfp;
    cudaGetSymbolAddress(&qkv_ptr, g_qkv);
    cudaGetSymbolAddress(&att_ptr, g_att);
    cudaGetSymbolAddress(&wfp, g_wfrag);

    cudaFuncSetAttribute(attn_hmma_kernel,
                         cudaFuncAttributeMaxDynamicSharedMemorySize, ATTN_SMEM);

    // 1. prep: bias+mask combine + W fragment image
    build_sbm_kernel<<<dim3((NN + 255) / 256, NWIN * HEADS), 256>>>(bias_table, rel_index, mask);
    split_w_kernel<<<64, 256>>>(qkv_w, proj_w);
    // 2. QKV projection (3 N-tiles)
    gemm_hmma<3><<<MTOT / 64, 256>>>(x, (const uint4*)wfp, qkv_b, (float*)qkv_ptr);
    // 3. attention
    attn_hmma_kernel<<<dim3(BATCH, HEADS), 256, ATTN_SMEM>>>();
    // 4. output projection (tile 3 of the fragment image)
    gemm_hmma<1><<<MTOT / 64, 256>>>(
        (const float*)att_ptr, (const uint4*)wfp + 12288, proj_b, out);
}

// round 12
// speedup vs baseline: 1.1048x; 1.1048x over previous
#include <cuda_runtime.h>
#include <cuda_bf16.h>
#include <stdint.h>
#include <math.h>

#define BATCH 2048
#define NTOK 98
#define DIM 128
#define HEADS 4
#define NWIN 256
#define NN (NTOK * NTOK)   // 9604
#define MTOT (BATCH * NTOK)  // 200704

// Scratch (device globals)
__device__ float g_qkv[(size_t)MTOT * 384];                 // [m][s*128+h*32+d]
__device__ float g_att[(size_t)MTOT * 128];                 // [m][h*32+d]
__device__ __nv_bfloat16 g_sbm[(size_t)NWIN * HEADS * NN];  // bias+mask bf16
__device__ uint4 g_wfrag[16384];                            // W in MMA-fragment layout

// ===========================================================================
__device__ __forceinline__ uint32_t smem_u32(const void* p) {
    uint32_t a;
    asm("{ .reg .u64 t; cvta.to.shared.u64 t, %1; cvt.u32.u64 %0, t; }" : "=r"(a) : "l"(p));
    return a;
}
__device__ __forceinline__ void ldsm_x4(uint32_t* r, uint32_t addr) {
    asm volatile("ldmatrix.sync.aligned.m8n8.x4.shared.b16 {%0,%1,%2,%3}, [%4];"
                 : "=r"(r[0]), "=r"(r[1]), "=r"(r[2]), "=r"(r[3]) : "r"(addr));
}
__device__ __forceinline__ void ldsm_x2(uint32_t* r, uint32_t addr) {
    asm volatile("ldmatrix.sync.aligned.m8n8.x2.shared.b16 {%0,%1}, [%2];"
                 : "=r"(r[0]), "=r"(r[1]) : "r"(addr));
}
__device__ __forceinline__ void ldsm_x4t(uint32_t* r, uint32_t addr) {
    asm volatile("ldmatrix.sync.aligned.m8n8.x4.trans.shared.b16 {%0,%1,%2,%3}, [%4];"
                 : "=r"(r[0]), "=r"(r[1]), "=r"(r[2]), "=r"(r[3]) : "r"(addr));
}
__device__ __forceinline__ void mma_bf16(float* d, const uint32_t* a, const uint32_t* b) {
    asm volatile("mma.sync.aligned.m16n8k16.row.col.f32.bf16.bf16.f32 "
                 "{%0,%1,%2,%3}, {%4,%5,%6,%7}, {%8,%9}, {%0,%1,%2,%3};"
                 : "+f"(d[0]), "+f"(d[1]), "+f"(d[2]), "+f"(d[3])
                 : "r"(a[0]), "r"(a[1]), "r"(a[2]), "r"(a[3]), "r"(b[0]), "r"(b[1]));
}
__device__ __forceinline__ uint32_t packbf(float a, float b) {
    __nv_bfloat162 t = __float22bfloat162_rn(make_float2(a, b));
    return *(uint32_t*)&t;
}
__device__ __forceinline__ float lopart(float v) {
    return v - __bfloat162float(__float2bfloat16(v));
}
__device__ __forceinline__ void split4(float4 v, uint2& hi, uint2& lo) {
    __nv_bfloat16 hx = __float2bfloat16(v.x), hy = __float2bfloat16(v.y);
    __nv_bfloat16 hz = __float2bfloat16(v.z), hw = __float2bfloat16(v.w);
    __nv_bfloat162 h0 = __halves2bfloat162(hx, hy), h1 = __halves2bfloat162(hz, hw);
    hi.x = *(uint32_t*)&h0; hi.y = *(uint32_t*)&h1;
    lo.x = packbf(v.x - __bfloat162float(hx), v.y - __bfloat162float(hy));
    lo.y = packbf(v.z - __bfloat162float(hz), v.w - __bfloat162float(hw));
}
// swizzled smem address: 256B-pitch rows, XOR 16B-chunk by row&7
__device__ __forceinline__ uint32_t swz(uint32_t r, uint32_t cb) {
    return (r << 8) + (cb ^ ((r & 7) << 4));
}

// ===========================================================================
// bias+mask combine
// ===========================================================================
__global__ void build_sbm_kernel(const float* __restrict__ table,
                                 const int* __restrict__ rel,
                                 const float* __restrict__ mask) {
    int nm = blockIdx.x * 256 + threadIdx.x;
    int wh = blockIdx.y;
    if (nm < NN) {
        int w = wh >> 2, h = wh & 3;
        float v = table[rel[nm] * HEADS + h] + mask[(size_t)w * NN + nm];
        g_sbm[(size_t)wh * NN + nm] = __float2bfloat16(v);
    }
}

// ===========================================================================
// W pre-split into MMA B-fragment layout.
// ===========================================================================
__global__ void split_w_kernel(const float* __restrict__ qkv_w,
                               const float* __restrict__ proj_w) {
    int idx = blockIdx.x * 256 + threadIdx.x;   // 16384
    int tile = idx >> 12;
    int rem = idx & 4095;
    int lane = rem & 31;
    int nblk = (rem >> 5) & 15;
    int kc = rem >> 9;
    int n = nblk * 8 + (lane >> 2);
    int k0 = kc * 16 + (lane & 3) * 2;
    const float* W = (tile < 3) ? qkv_w + (size_t)(tile * 128 + n) * 128
                                : proj_w + (size_t)n * 128;
    float2 a = *(const float2*)(W + k0);
    float2 b = *(const float2*)(W + k0 + 8);
    uint4 o;
    {
        __nv_bfloat162 h = __halves2bfloat162(__float2bfloat16(a.x), __float2bfloat16(a.y));
        o.x = *(uint32_t*)&h;
        __nv_bfloat162 h2 = __halves2bfloat162(__float2bfloat16(b.x), __float2bfloat16(b.y));
        o.y = *(uint32_t*)&h2;
    }
    o.z = packbf(lopart(a.x), lopart(a.y));
    o.w = packbf(lopart(b.x), lopart(b.y));
    g_wfrag[idx] = o;
}

// ===========================================================================
// HMMA GEMM (unchanged from R9): 64M x NITER*128N, W frags from L2.
// ===========================================================================
template<int NITER>
__global__ __launch_bounds__(256, 3) void gemm_hmma(
    const float* __restrict__ Af, const uint4* __restrict__ Wfrag,
    const float* __restrict__ bias, float* __restrict__ Cf)
{
    __shared__ char sm[32768];
    const uint32_t smb = smem_u32(sm);
    const int tid = threadIdx.x;
    const int wid = tid >> 5, lane = tid & 31;
    const size_t m0 = (size_t)blockIdx.x * 64;
    const int N = NITER * 128;

#pragma unroll
    for (int i = 0; i < 8; i++) {
        int idx = tid + 256 * i;
        int r = idx >> 5;
        int c4 = (idx & 31) << 2;
        float4 v = *(const float4*)(Af + (m0 + r) * 128 + c4);
        uint2 hi, lo;
        split4(v, hi, lo);
        *(uint2*)(sm + swz(r, c4 * 2)) = hi;
        *(uint2*)(sm + 16384 + swz(r, c4 * 2)) = lo;
    }
    __syncthreads();

    const int wm = (wid & 1) * 32;
    const int wnb = (wid >> 1) * 4;
    const int rq = lane >> 2, cq = (lane & 3) * 2;

#pragma unroll 1
    for (int it = 0; it < NITER; it++) {
        const int n0 = it * 128;

        float acc[2][4][4];
#pragma unroll
        for (int mi = 0; mi < 2; mi++)
#pragma unroll
            for (int ni = 0; ni < 4; ni++)
#pragma unroll
                for (int c = 0; c < 4; c++) acc[mi][ni][c] = 0.f;

#pragma unroll
        for (int kc = 0; kc < 8; kc++) {
            uint32_t cb = (uint32_t)(kc * 32 + ((lane >> 4) & 1) * 16);
            uint32_t ah[2][4], al[2][4];
#pragma unroll
            for (int mi = 0; mi < 2; mi++) {
                uint32_t r = (uint32_t)(wm + mi * 16 + (lane & 15));
                ldsm_x4(ah[mi], smb + swz(r, cb));
                ldsm_x4(al[mi], smb + 16384 + swz(r, cb));
            }
            const uint4* wp = Wfrag + ((size_t)(it * 8 + kc) * 16 + wnb) * 32 + lane;
#pragma unroll
            for (int ni = 0; ni < 4; ni++) {
                uint4 w = wp[ni * 32];
                uint32_t B0[2] = {w.x, w.y};
                uint32_t Bl[2] = {w.z, w.w};
#pragma unroll
                for (int mi = 0; mi < 2; mi++) {
                    mma_bf16(acc[mi][ni], ah[mi], B0);
                    mma_bf16(acc[mi][ni], al[mi], B0);
                    mma_bf16(acc[mi][ni], ah[mi], Bl);
                }
            }
        }

#pragma unroll
        for (int mi = 0; mi < 2; mi++) {
            size_t rA = m0 + wm + mi * 16 + rq;
            size_t rB = rA + 8;
#pragma unroll
            for (int ni = 0; ni < 4; ni++) {
                int col = n0 + wnb * 8 + ni * 8 + cq;
                float b0 = bias[col], b1 = bias[col + 1];
                *(float2*)(Cf + rA * N + col) =
                    make_float2(acc[mi][ni][0] + b0, acc[mi][ni][1] + b1);
                *(float2*)(Cf + rB * N + col) =
                    make_float2(acc[mi][ni][2] + b0, acc[mi][ni][3] + b1);
            }
        }
    }
}

// ===========================================================================
// HMMA attention: one CTA per (window, head), 256 threads (8 warps x 16 rows).
// Single kc loop; B-side hi/lo fragments loaded once and shared across the
// three split-products (Ah*Bh + Ah*Bl + Al*Bh).
// ===========================================================================
#define PITCH 80
#define QH_OFF 0
#define QL_OFF 10240
#define KH_OFF 20480
#define KL_OFF 29440
#define VH_OFF 38400
#define VL_OFF 47360
#define ATTN_SMEM 56320

__global__ __launch_bounds__(256, 3) void attn_hmma_kernel() {
    extern __shared__ char smraw[];
    const uint32_t smb = smem_u32(smraw);
    char* sm = smraw;

    const int b = blockIdx.x, h = blockIdx.y;
    const int tid = threadIdx.x;
    const int wid = tid >> 5, lane = tid & 31;

    // ---- zero only pad rows (98..111) of all 6 tiles ----
    {
        uint4 z = make_uint4(0, 0, 0, 0);
        for (int idx = tid; idx < 420; idx += 256) {
            int t = idx / 70;
            int rem = idx - t * 70;
            int row = 98 + rem / 5;
            int ch = rem % 5;
            uint32_t base = (t < 2) ? (uint32_t)(t * 10240)
                                    : (uint32_t)(20480 + (t - 2) * 8960);
            *(uint4*)(sm + base + row * PITCH + ch * 16) = z;
        }
    }
    __syncthreads();

    // ---- load Q (scaled) / K / V, split hi/lo bf16, 16B stores ----
    const float scale = 0.17677669529663687f;
    const float* qg = g_qkv + ((size_t)b * NTOK) * 384 + h * 32;
    for (int idx = tid; idx < NTOK * 4; idx += 256) {
        int n = idx >> 2, c8 = (idx & 3) << 3;
        const float* src = qg + (size_t)n * 384 + c8;
        uint32_t off = (uint32_t)(n * PITCH + c8 * 2);
        uint2 h0, l0, h1, l1;

        float4 qa = *(const float4*)src;
        float4 qb = *(const float4*)(src + 4);
        qa.x *= scale; qa.y *= scale; qa.z *= scale; qa.w *= scale;
        qb.x *= scale; qb.y *= scale; qb.z *= scale; qb.w *= scale;
        split4(qa, h0, l0); split4(qb, h1, l1);
        *(uint4*)(sm + QH_OFF + off) = make_uint4(h0.x, h0.y, h1.x, h1.y);
        *(uint4*)(sm + QL_OFF + off) = make_uint4(l0.x, l0.y, l1.x, l1.y);

        split4(*(const float4*)(src + 128), h0, l0);
        split4(*(const float4*)(src + 132), h1, l1);
        *(uint4*)(sm + KH_OFF + off) = make_uint4(h0.x, h0.y, h1.x, h1.y);
        *(uint4*)(sm + KL_OFF + off) = make_uint4(l0.x, l0.y, l1.x, l1.y);

        split4(*(const float4*)(src + 256), h0, l0);
        split4(*(const float4*)(src + 260), h1, l1);
        *(uint4*)(sm + VH_OFF + off) = make_uint4(h0.x, h0.y, h1.x, h1.y);
        *(uint4*)(sm + VL_OFF + off) = make_uint4(l0.x, l0.y, l1.x, l1.y);
    }
    __syncthreads();

    if (wid == 7) return;   // rows 112..127 are pure padding

    const int l8 = lane & 7;
    const int rq = lane >> 2;
    const int cq = (lane & 3) * 2;
    const int sel16 = (lane >> 4) & 1;

    // ---- S = QK^T: single kc loop, 3 products share fragments ----
    float acc[13][4];
#pragma unroll
    for (int nt = 0; nt < 13; nt++)
#pragma unroll
        for (int c = 0; c < 4; c++) acc[nt][c] = 0.f;

#pragma unroll
    for (int kc = 0; kc < 2; kc++) {
        uint32_t r = (uint32_t)(wid * 16 + (lane & 15));
        uint32_t aoff = (uint32_t)(kc * 32 + sel16 * 16);
        uint32_t qh[4], ql[4];
        ldsm_x4(qh, smb + QH_OFF + r * PITCH + aoff);
        ldsm_x4(ql, smb + QL_OFF + r * PITCH + aoff);
        uint32_t boff = (uint32_t)(kc * 32 + ((lane >> 3) & 1) * 16);
#pragma unroll
        for (int nt2 = 0; nt2 < 6; nt2++) {
            uint32_t row = (uint32_t)((2 * nt2 + sel16) * 8 + l8);
            uint32_t kh[4], kl[4];
            ldsm_x4(kh, smb + KH_OFF + row * PITCH + boff);
            ldsm_x4(kl, smb + KL_OFF + row * PITCH + boff);
            mma_bf16(acc[2 * nt2], qh, kh);
            mma_bf16(acc[2 * nt2], qh, kl);
            mma_bf16(acc[2 * nt2], ql, kh);
            mma_bf16(acc[2 * nt2 + 1], qh, kh + 2);
            mma_bf16(acc[2 * nt2 + 1], qh, kl + 2);
            mma_bf16(acc[2 * nt2 + 1], ql, kh + 2);
        }
        {
            uint32_t kh[2], kl[2];
            ldsm_x2(kh, smb + KH_OFF + (uint32_t)(96 + l8) * PITCH + boff);
            ldsm_x2(kl, smb + KL_OFF + (uint32_t)(96 + l8) * PITCH + boff);
            mma_bf16(acc[12], qh, kh);
            mma_bf16(acc[12], qh, kl);
            mma_bf16(acc[12], ql, kh);
        }
    }

    // ---- bias+mask add (direct from gmem), softmax ----
    const __nv_bfloat16* sbm = g_sbm + ((size_t)((b & (NWIN - 1)) * HEADS + h)) * NN;
    const int rA = wid * 16 + rq;
    const int rB = rA + 8;
    float mxA = -1e30f, mxB = -1e30f;
#pragma unroll
    for (int nt = 0; nt < 13; nt++) {
        int col = nt * 8 + cq;
        if (col < 98) {
            if (rA < 98) {
                uint32_t u = __ldg((const uint32_t*)(sbm + rA * 98 + col));
                __nv_bfloat162 bb = *(__nv_bfloat162*)&u;
                acc[nt][0] += __bfloat162float(bb.x);
                acc[nt][1] += __bfloat162float(bb.y);
            }
            if (rB < 98) {
                uint32_t u = __ldg((const uint32_t*)(sbm + rB * 98 + col));
                __nv_bfloat162 bb = *(__nv_bfloat162*)&u;
                acc[nt][2] += __bfloat162float(bb.x);
                acc[nt][3] += __bfloat162float(bb.y);
            }
        } else {
            acc[nt][0] = -1e30f; acc[nt][1] = -1e30f;
            acc[nt][2] = -1e30f; acc[nt][3] = -1e30f;
        }
        mxA = fmaxf(mxA, fmaxf(acc[nt][0], acc[nt][1]));
        mxB = fmaxf(mxB, fmaxf(acc[nt][2], acc[nt][3]));
    }
    mxA = fmaxf(mxA, __shfl_xor_sync(0xffffffffu, mxA, 1));
    mxA = fmaxf(mxA, __shfl_xor_sync(0xffffffffu, mxA, 2));
    mxB = fmaxf(mxB, __shfl_xor_sync(0xffffffffu, mxB, 1));
    mxB = fmaxf(mxB, __shfl_xor_sync(0xffffffffu, mxB, 2));
    float sA = 0.f, sB = 0.f;
#pragma unroll
    for (int nt = 0; nt < 13; nt++) {
        float e0 = __expf(acc[nt][0] - mxA);
        float e1 = __expf(acc[nt][1] - mxA);
        float e2 = __expf(acc[nt][2] - mxB);
        float e3 = __expf(acc[nt][3] - mxB);
        acc[nt][0] = e0; acc[nt][1] = e1;
        acc[nt][2] = e2; acc[nt][3] = e3;
        sA += e0 + e1; sB += e2 + e3;
    }
    sA += __shfl_xor_sync(0xffffffffu, sA, 1);
    sA += __shfl_xor_sync(0xffffffffu, sA, 2);
    sB += __shfl_xor_sync(0xffffffffu, sB, 1);
    sB += __shfl_xor_sync(0xffffffffu, sB, 2);

    // ---- O = P V: single kc loop, 3 products share V fragments ----
    float oacc[4][4];
#pragma unroll
    for (int nh = 0; nh < 4; nh++)
#pragma unroll
        for (int c = 0; c < 4; c++) oacc[nh][c] = 0.f;

#pragma unroll
    for (int kc = 0; kc < 7; kc++) {
        int nt0 = 2 * kc, nt1 = nt0 + 1;
        float v0 = acc[nt0][0], v1 = acc[nt0][1];
        float v2 = acc[nt0][2], v3 = acc[nt0][3];
        float w0 = 0.f, w1 = 0.f, w2 = 0.f, w3 = 0.f;
        if (nt1 < 13) {
            w0 = acc[nt1][0]; w1 = acc[nt1][1];
            w2 = acc[nt1][2]; w3 = acc[nt1][3];
        }
        uint32_t amh[4], aml[4];
        amh[0] = packbf(v0, v1);
        amh[1] = packbf(v2, v3);
        amh[2] = packbf(w0, w1);
        amh[3] = packbf(w2, w3);
        aml[0] = packbf(lopart(v0), lopart(v1));
        aml[1] = packbf(lopart(v2), lopart(v3));
        aml[2] = packbf(lopart(w0), lopart(w1));
        aml[3] = packbf(lopart(w2), lopart(w3));
        uint32_t vrow = (uint32_t)(kc * 16 + ((lane >> 3) & 1) * 8 + l8);
#pragma unroll
        for (int nh2 = 0; nh2 < 2; nh2++) {
            uint32_t coff = (uint32_t)((2 * nh2 + sel16) * 16);
            uint32_t vh[4], vl[4];
            ldsm_x4t(vh, smb + VH_OFF + vrow * PITCH + coff);
            ldsm_x4t(vl, smb + VL_OFF + vrow * PITCH + coff);
            mma_bf16(oacc[2 * nh2], amh, vh);
            mma_bf16(oacc[2 * nh2], amh, vl);
            mma_bf16(oacc[2 * nh2], aml, vh);
            mma_bf16(oacc[2 * nh2 + 1], amh, vh + 2);
            mma_bf16(oacc[2 * nh2 + 1], amh, vl + 2);
            mma_bf16(oacc[2 * nh2 + 1], aml, vh + 2);
        }
    }

    // ---- epilogue ----
    float invA = 1.0f / sA;
    float invB = 1.0f / sB;
#pragma unroll
    for (int nh = 0; nh < 4; nh++) {
        int col = nh * 8 + cq;
        if (rA < 98) {
            float2 o = make_float2(oacc[nh][0] * invA, oacc[nh][1] * invA);
            *(float2*)(g_att + ((size_t)b * NTOK + rA) * 128 + h * 32 + col) = o;
        }
        if (rB < 98) {
            float2 o = make_float2(oacc[nh][2] * invB, oacc[nh][3] * invB);
            *(float2*)(g_att + ((size_t)b * NTOK + rB) * 128 + h * 32 + col) = o;
        }
    }
}

// ===========================================================================
extern "C" void kernel_launch(void* const* d_in, const int* in_sizes, int n_in,
                              void* d_out, int out_size) {
    const float* x          = (const float*)d_in[0];
    const float* mask       = (const float*)d_in[1];
    const float* qkv_w      = (const float*)d_in[2];
    const float* qkv_b      = (const float*)d_in[3];
    const float* proj_w     = (const float*)d_in[4];
    const float* proj_b     = (const float*)d_in[5];
    const float* bias_table = (const float*)d_in[6];
    const int*   rel_index  = (const int*)d_in[7];
    float* out = (float*)d_out;

    void *qkv_ptr, *att_ptr, *wfp;
    cudaGetSymbolAddress(&qkv_ptr, g_qkv);
    cudaGetSymbolAddress(&att_ptr, g_att);
    cudaGetSymbolAddress(&wfp, g_wfrag);

    cudaFuncSetAttribute(attn_hmma_kernel,
                         cudaFuncAttributeMaxDynamicSharedMemorySize, ATTN_SMEM);

    // 1. prep: bias+mask combine + W fragment image
    build_sbm_kernel<<<dim3((NN + 255) / 256, NWIN * HEADS), 256>>>(bias_table, rel_index, mask);
    split_w_kernel<<<64, 256>>>(qkv_w, proj_w);
    // 2. QKV projection (3 N-tiles)
    gemm_hmma<3><<<MTOT / 64, 256>>>(x, (const uint4*)wfp, qkv_b, (float*)qkv_ptr);
    // 3. attention
    attn_hmma_kernel<<<dim3(BATCH, HEADS), 256, ATTN_SMEM>>>();
    // 4. output projection (tile 3 of the fragment image)
    gemm_hmma<1><<<MTOT / 64, 256>>>(
        (const float*)att_ptr, (const uint4*)wfp + 12288, proj_b, out);
}

// round 14
// speedup vs baseline: 1.1266x; 1.0197x over previous
#include <cuda_runtime.h>
#include <cuda_bf16.h>
#include <stdint.h>
#include <math.h>

#define BATCH 2048
#define NTOK 98
#define DIM 128
#define HEADS 4
#define NWIN 256
#define NN (NTOK * NTOK)   // 9604
#define MTOT (BATCH * NTOK)  // 200704

// Scratch (device globals)
__device__ float g_qkv[(size_t)MTOT * 384];                 // [m][s*128+h*32+d]
__device__ float g_att[(size_t)MTOT * 128];                 // [m][h*32+d]
__device__ __nv_bfloat16 g_sbm[(size_t)NWIN * HEADS * NN];  // (bias+mask)*log2e bf16
__device__ uint4 g_wfrag[16384];                            // W in MMA-fragment layout

// ===========================================================================
__device__ __forceinline__ uint32_t smem_u32(const void* p) {
    uint32_t a;
    asm("{ .reg .u64 t; cvta.to.shared.u64 t, %1; cvt.u32.u64 %0, t; }" : "=r"(a) : "l"(p));
    return a;
}
__device__ __forceinline__ void ldsm_x4(uint32_t* r, uint32_t addr) {
    asm volatile("ldmatrix.sync.aligned.m8n8.x4.shared.b16 {%0,%1,%2,%3}, [%4];"
                 : "=r"(r[0]), "=r"(r[1]), "=r"(r[2]), "=r"(r[3]) : "r"(addr));
}
__device__ __forceinline__ void ldsm_x2(uint32_t* r, uint32_t addr) {
    asm volatile("ldmatrix.sync.aligned.m8n8.x2.shared.b16 {%0,%1}, [%2];"
                 : "=r"(r[0]), "=r"(r[1]) : "r"(addr));
}
__device__ __forceinline__ void ldsm_x4t(uint32_t* r, uint32_t addr) {
    asm volatile("ldmatrix.sync.aligned.m8n8.x4.trans.shared.b16 {%0,%1,%2,%3}, [%4];"
                 : "=r"(r[0]), "=r"(r[1]), "=r"(r[2]), "=r"(r[3]) : "r"(addr));
}
__device__ __forceinline__ void mma_bf16(float* d, const uint32_t* a, const uint32_t* b) {
    asm volatile("mma.sync.aligned.m16n8k16.row.col.f32.bf16.bf16.f32 "
                 "{%0,%1,%2,%3}, {%4,%5,%6,%7}, {%8,%9}, {%0,%1,%2,%3};"
                 : "+f"(d[0]), "+f"(d[1]), "+f"(d[2]), "+f"(d[3])
                 : "r"(a[0]), "r"(a[1]), "r"(a[2]), "r"(a[3]), "r"(b[0]), "r"(b[1]));
}
__device__ __forceinline__ float ex2f(float x) {
    float y;
    asm("ex2.approx.ftz.f32 %0, %1;" : "=f"(y) : "f"(x));
    return y;
}
__device__ __forceinline__ uint32_t packbf(float a, float b) {
    __nv_bfloat162 t = __float22bfloat162_rn(make_float2(a, b));
    return *(uint32_t*)&t;
}
__device__ __forceinline__ float lopart(float v) {
    return v - __bfloat162float(__float2bfloat16(v));
}
__device__ __forceinline__ void split4(float4 v, uint2& hi, uint2& lo) {
    __nv_bfloat16 hx = __float2bfloat16(v.x), hy = __float2bfloat16(v.y);
    __nv_bfloat16 hz = __float2bfloat16(v.z), hw = __float2bfloat16(v.w);
    __nv_bfloat162 h0 = __halves2bfloat162(hx, hy), h1 = __halves2bfloat162(hz, hw);
    hi.x = *(uint32_t*)&h0; hi.y = *(uint32_t*)&h1;
    lo.x = packbf(v.x - __bfloat162float(hx), v.y - __bfloat162float(hy));
    lo.y = packbf(v.z - __bfloat162float(hz), v.w - __bfloat162float(hw));
}
// truncation split of a float pair into hi (PRMT) and lo (residual)
__device__ __forceinline__ void tsplit2(float v0, float v1, uint32_t& hi, uint32_t& lo) {
    uint32_t b0 = __float_as_uint(v0), b1 = __float_as_uint(v1);
    hi = __byte_perm(b0, b1, 0x7632);
    float h0 = __uint_as_float(b0 & 0xFFFF0000u);
    float h1 = __uint_as_float(b1 & 0xFFFF0000u);
    lo = packbf(v0 - h0, v1 - h1);
}
// swizzled smem address: 256B-pitch rows, XOR 16B-chunk by row&7
__device__ __forceinline__ uint32_t swz(uint32_t r, uint32_t cb) {
    return (r << 8) + (cb ^ ((r & 7) << 4));
}

#define LOG2E 1.4426950408889634f

// ===========================================================================
// bias+mask combine (pre-scaled by log2e for exp2 softmax)
// ===========================================================================
__global__ void build_sbm_kernel(const float* __restrict__ table,
                                 const int* __restrict__ rel,
                                 const float* __restrict__ mask) {
    int nm = blockIdx.x * 256 + threadIdx.x;
    int wh = blockIdx.y;
    if (nm < NN) {
        int w = wh >> 2, h = wh & 3;
        float v = (table[rel[nm] * HEADS + h] + mask[(size_t)w * NN + nm]) * LOG2E;
        g_sbm[(size_t)wh * NN + nm] = __float2bfloat16(v);
    }
}

// ===========================================================================
// W pre-split into MMA B-fragment layout.
// ===========================================================================
__global__ void split_w_kernel(const float* __restrict__ qkv_w,
                               const float* __restrict__ proj_w) {
    int idx = blockIdx.x * 256 + threadIdx.x;   // 16384
    int tile = idx >> 12;
    int rem = idx & 4095;
    int lane = rem & 31;
    int nblk = (rem >> 5) & 15;
    int kc = rem >> 9;
    int n = nblk * 8 + (lane >> 2);
    int k0 = kc * 16 + (lane & 3) * 2;
    const float* W = (tile < 3) ? qkv_w + (size_t)(tile * 128 + n) * 128
                                : proj_w + (size_t)n * 128;
    float2 a = *(const float2*)(W + k0);
    float2 b = *(const float2*)(W + k0 + 8);
    uint4 o;
    {
        __nv_bfloat162 h = __halves2bfloat162(__float2bfloat16(a.x), __float2bfloat16(a.y));
        o.x = *(uint32_t*)&h;
        __nv_bfloat162 h2 = __halves2bfloat162(__float2bfloat16(b.x), __float2bfloat16(b.y));
        o.y = *(uint32_t*)&h2;
    }
    o.z = packbf(lopart(a.x), lopart(a.y));
    o.w = packbf(lopart(b.x), lopart(b.y));
    g_wfrag[idx] = o;
}

// ===========================================================================
// HMMA GEMM (unchanged): 64M x NITER*128N, W frags from L2.
// ===========================================================================
template<int NITER>
__global__ __launch_bounds__(256, 3) void gemm_hmma(
    const float* __restrict__ Af, const uint4* __restrict__ Wfrag,
    const float* __restrict__ bias, float* __restrict__ Cf)
{
    __shared__ char sm[32768];
    const uint32_t smb = smem_u32(sm);
    const int tid = threadIdx.x;
    const int wid = tid >> 5, lane = tid & 31;
    const size_t m0 = (size_t)blockIdx.x * 64;
    const int N = NITER * 128;

#pragma unroll
    for (int i = 0; i < 8; i++) {
        int idx = tid + 256 * i;
        int r = idx >> 5;
        int c4 = (idx & 31) << 2;
        float4 v = *(const float4*)(Af + (m0 + r) * 128 + c4);
        uint2 hi, lo;
        split4(v, hi, lo);
        *(uint2*)(sm + swz(r, c4 * 2)) = hi;
        *(uint2*)(sm + 16384 + swz(r, c4 * 2)) = lo;
    }
    __syncthreads();

    const int wm = (wid & 1) * 32;
    const int wnb = (wid >> 1) * 4;
    const int rq = lane >> 2, cq = (lane & 3) * 2;

#pragma unroll 1
    for (int it = 0; it < NITER; it++) {
        const int n0 = it * 128;

        float acc[2][4][4];
#pragma unroll
        for (int mi = 0; mi < 2; mi++)
#pragma unroll
            for (int ni = 0; ni < 4; ni++)
#pragma unroll
                for (int c = 0; c < 4; c++) acc[mi][ni][c] = 0.f;

#pragma unroll
        for (int kc = 0; kc < 8; kc++) {
            uint32_t cb = (uint32_t)(kc * 32 + ((lane >> 4) & 1) * 16);
            uint32_t ah[2][4], al[2][4];
#pragma unroll
            for (int mi = 0; mi < 2; mi++) {
                uint32_t r = (uint32_t)(wm + mi * 16 + (lane & 15));
                ldsm_x4(ah[mi], smb + swz(r, cb));
                ldsm_x4(al[mi], smb + 16384 + swz(r, cb));
            }
            const uint4* wp = Wfrag + ((size_t)(it * 8 + kc) * 16 + wnb) * 32 + lane;
#pragma unroll
            for (int ni = 0; ni < 4; ni++) {
                uint4 w = wp[ni * 32];
                uint32_t B0[2] = {w.x, w.y};
                uint32_t Bl[2] = {w.z, w.w};
#pragma unroll
                for (int mi = 0; mi < 2; mi++) {
                    mma_bf16(acc[mi][ni], ah[mi], B0);
                    mma_bf16(acc[mi][ni], al[mi], B0);
                    mma_bf16(acc[mi][ni], ah[mi], Bl);
                }
            }
        }

#pragma unroll
        for (int mi = 0; mi < 2; mi++) {
            size_t rA = m0 + wm + mi * 16 + rq;
            size_t rB = rA + 8;
#pragma unroll
            for (int ni = 0; ni < 4; ni++) {
                int col = n0 + wnb * 8 + ni * 8 + cq;
                float b0 = bias[col], b1 = bias[col + 1];
                *(float2*)(Cf + rA * N + col) =
                    make_float2(acc[mi][ni][0] + b0, acc[mi][ni][1] + b1);
                *(float2*)(Cf + rB * N + col) =
                    make_float2(acc[mi][ni][2] + b0, acc[mi][ni][3] + b1);
            }
        }
    }
}

// ===========================================================================
// HMMA attention: one CTA per (window, head), 256 threads (8 warps x 16 rows).
// No-max softmax via exp2 (log2e folded into q-scale and sbm); fused
// bias+exp+sum loop; truncation split for P fragments.
// ===========================================================================
#define PITCH 80
#define QH_OFF 0
#define QL_OFF 10240
#define KH_OFF 20480
#define KL_OFF 29440
#define VH_OFF 38400
#define VL_OFF 47360
#define ATTN_SMEM 56320

__global__ __launch_bounds__(256, 3) void attn_hmma_kernel() {
    extern __shared__ char smraw[];
    const uint32_t smb = smem_u32(smraw);
    char* sm = smraw;

    const int b = blockIdx.x, h = blockIdx.y;
    const int tid = threadIdx.x;
    const int wid = tid >> 5, lane = tid & 31;

    // ---- zero only pad rows (98..111) of all 6 tiles ----
    {
        uint4 z = make_uint4(0, 0, 0, 0);
        for (int idx = tid; idx < 420; idx += 256) {
            int t = idx / 70;
            int rem = idx - t * 70;
            int row = 98 + rem / 5;
            int ch = rem % 5;
            uint32_t base = (t < 2) ? (uint32_t)(t * 10240)
                                    : (uint32_t)(20480 + (t - 2) * 8960);
            *(uint4*)(sm + base + row * PITCH + ch * 16) = z;
        }
    }
    __syncthreads();

    // ---- load Q (scaled by scale*log2e) / K / V, split hi/lo ----
    const float qscale = 0.17677669529663687f * LOG2E;
    const float* qg = g_qkv + ((size_t)b * NTOK) * 384 + h * 32;
    for (int idx = tid; idx < NTOK * 4; idx += 256) {
        int n = idx >> 2, c8 = (idx & 3) << 3;
        const float* src = qg + (size_t)n * 384 + c8;
        uint32_t off = (uint32_t)(n * PITCH + c8 * 2);
        uint2 h0, l0, h1, l1;

        float4 qa = *(const float4*)src;
        float4 qb = *(const float4*)(src + 4);
        qa.x *= qscale; qa.y *= qscale; qa.z *= qscale; qa.w *= qscale;
        qb.x *= qscale; qb.y *= qscale; qb.z *= qscale; qb.w *= qscale;
        split4(qa, h0, l0); split4(qb, h1, l1);
        *(uint4*)(sm + QH_OFF + off) = make_uint4(h0.x, h0.y, h1.x, h1.y);
        *(uint4*)(sm + QL_OFF + off) = make_uint4(l0.x, l0.y, l1.x, l1.y);

        split4(*(const float4*)(src + 128), h0, l0);
        split4(*(const float4*)(src + 132), h1, l1);
        *(uint4*)(sm + KH_OFF + off) = make_uint4(h0.x, h0.y, h1.x, h1.y);
        *(uint4*)(sm + KL_OFF + off) = make_uint4(l0.x, l0.y, l1.x, l1.y);

        split4(*(const float4*)(src + 256), h0, l0);
        split4(*(const float4*)(src + 260), h1, l1);
        *(uint4*)(sm + VH_OFF + off) = make_uint4(h0.x, h0.y, h1.x, h1.y);
        *(uint4*)(sm + VL_OFF + off) = make_uint4(l0.x, l0.y, l1.x, l1.y);
    }
    __syncthreads();

    if (wid == 7) return;   // rows 112..127 are pure padding

    const int l8 = lane & 7;
    const int rq = lane >> 2;
    const int cq = (lane & 3) * 2;
    const int sel16 = (lane >> 4) & 1;

    // ---- S = QK^T: single kc loop, 3 products share fragments ----
    float acc[13][4];
#pragma unroll
    for (int nt = 0; nt < 13; nt++)
#pragma unroll
        for (int c = 0; c < 4; c++) acc[nt][c] = 0.f;

#pragma unroll
    for (int kc = 0; kc < 2; kc++) {
        uint32_t r = (uint32_t)(wid * 16 + (lane & 15));
        uint32_t aoff = (uint32_t)(kc * 32 + sel16 * 16);
        uint32_t qh[4], ql[4];
        ldsm_x4(qh, smb + QH_OFF + r * PITCH + aoff);
        ldsm_x4(ql, smb + QL_OFF + r * PITCH + aoff);
        uint32_t boff = (uint32_t)(kc * 32 + ((lane >> 3) & 1) * 16);
#pragma unroll
        for (int nt2 = 0; nt2 < 6; nt2++) {
            uint32_t row = (uint32_t)((2 * nt2 + sel16) * 8 + l8);
            uint32_t kh[4], kl[4];
            ldsm_x4(kh, smb + KH_OFF + row * PITCH + boff);
            ldsm_x4(kl, smb + KL_OFF + row * PITCH + boff);
            mma_bf16(acc[2 * nt2], qh, kh);
            mma_bf16(acc[2 * nt2], qh, kl);
            mma_bf16(acc[2 * nt2], ql, kh);
            mma_bf16(acc[2 * nt2 + 1], qh, kh + 2);
            mma_bf16(acc[2 * nt2 + 1], qh, kl + 2);
            mma_bf16(acc[2 * nt2 + 1], ql, kh + 2);
        }
        {
            uint32_t kh[2], kl[2];
            ldsm_x2(kh, smb + KH_OFF + (uint32_t)(96 + l8) * PITCH + boff);
            ldsm_x2(kl, smb + KL_OFF + (uint32_t)(96 + l8) * PITCH + boff);
            mma_bf16(acc[12], qh, kh);
            mma_bf16(acc[12], qh, kl);
            mma_bf16(acc[12], ql, kh);
        }
    }

    // ---- fused bias + exp2 + rowsum (no max pass) ----
    const __nv_bfloat16* sbm = g_sbm + ((size_t)((b & (NWIN - 1)) * HEADS + h)) * NN;
    const int rA = wid * 16 + rq;
    const int rB = rA + 8;
    float sA = 0.f, sB = 0.f;
#pragma unroll
    for (int nt = 0; nt < 13; nt++) {
        int col = nt * 8 + cq;
        float f0 = -1e30f, f1 = -1e30f, f2 = -1e30f, f3 = -1e30f;
        if (col < 98) {
            if (rA < 98) {
                uint32_t u = __ldg((const uint32_t*)(sbm + rA * 98 + col));
                __nv_bfloat162 bb = *(__nv_bfloat162*)&u;
                f0 = acc[nt][0] + __bfloat162float(bb.x);
                f1 = acc[nt][1] + __bfloat162float(bb.y);
            }
            if (rB < 98) {
                uint32_t u = __ldg((const uint32_t*)(sbm + rB * 98 + col));
                __nv_bfloat162 bb = *(__nv_bfloat162*)&u;
                f2 = acc[nt][2] + __bfloat162float(bb.x);
                f3 = acc[nt][3] + __bfloat162float(bb.y);
            }
        }
        float e0 = ex2f(f0), e1 = ex2f(f1), e2 = ex2f(f2), e3 = ex2f(f3);
        acc[nt][0] = e0; acc[nt][1] = e1;
        acc[nt][2] = e2; acc[nt][3] = e3;
        sA += e0 + e1; sB += e2 + e3;
    }
    sA += __shfl_xor_sync(0xffffffffu, sA, 1);
    sA += __shfl_xor_sync(0xffffffffu, sA, 2);
    sB += __shfl_xor_sync(0xffffffffu, sB, 1);
    sB += __shfl_xor_sync(0xffffffffu, sB, 2);

    // ---- O = P V: single kc loop, 3 products share V fragments ----
    float oacc[4][4];
#pragma unroll
    for (int nh = 0; nh < 4; nh++)
#pragma unroll
        for (int c = 0; c < 4; c++) oacc[nh][c] = 0.f;

#pragma unroll
    for (int kc = 0; kc < 7; kc++) {
        int nt0 = 2 * kc, nt1 = nt0 + 1;
        float w0 = 0.f, w1 = 0.f, w2 = 0.f, w3 = 0.f;
        if (nt1 < 13) {
            w0 = acc[nt1][0]; w1 = acc[nt1][1];
            w2 = acc[nt1][2]; w3 = acc[nt1][3];
        }
        uint32_t amh[4], aml[4];
        tsplit2(acc[nt0][0], acc[nt0][1], amh[0], aml[0]);
        tsplit2(acc[nt0][2], acc[nt0][3], amh[1], aml[1]);
        tsplit2(w0, w1, amh[2], aml[2]);
        tsplit2(w2, w3, amh[3], aml[3]);
        uint32_t vrow = (uint32_t)(kc * 16 + ((lane >> 3) & 1) * 8 + l8);
#pragma unroll
        for (int nh2 = 0; nh2 < 2; nh2++) {
            uint32_t coff = (uint32_t)((2 * nh2 + sel16) * 16);
            uint32_t vh[4], vl[4];
            ldsm_x4t(vh, smb + VH_OFF + vrow * PITCH + coff);
            ldsm_x4t(vl, smb + VL_OFF + vrow * PITCH + coff);
            mma_bf16(oacc[2 * nh2], amh, vh);
            mma_bf16(oacc[2 * nh2], amh, vl);
            mma_bf16(oacc[2 * nh2], aml, vh);
            mma_bf16(oacc[2 * nh2 + 1], amh, vh + 2);
            mma_bf16(oacc[2 * nh2 + 1], amh, vl + 2);
            mma_bf16(oacc[2 * nh2 + 1], aml, vh + 2);
        }
    }

    // ---- epilogue ----
    float invA = 1.0f / sA;
    float invB = 1.0f / sB;
#pragma unroll
    for (int nh = 0; nh < 4; nh++) {
        int col = nh * 8 + cq;
        if (rA < 98) {
            float2 o = make_float2(oacc[nh][0] * invA, oacc[nh][1] * invA);
            *(float2*)(g_att + ((size_t)b * NTOK + rA) * 128 + h * 32 + col) = o;
        }
        if (rB < 98) {
            float2 o = make_float2(oacc[nh][2] * invB, oacc[nh][3] * invB);
            *(float2*)(g_att + ((size_t)b * NTOK + rB) * 128 + h * 32 + col) = o;
        }
    }
}

// ===========================================================================
extern "C" void kernel_launch(void* const* d_in, const int* in_sizes, int n_in,
                              void* d_out, int out_size) {
    const float* x          = (const float*)d_in[0];
    const float* mask       = (const float*)d_in[1];
    const float* qkv_w      = (const float*)d_in[2];
    const float* qkv_b      = (const float*)d_in[3];
    const float* proj_w     = (const float*)d_in[4];
    const float* proj_b     = (const float*)d_in[5];
    const float* bias_table = (const float*)d_in[6];
    const int*   rel_index  = (const int*)d_in[7];
    float* out = (float*)d_out;

    void *qkv_ptr, *att_ptr, *wfp;
    cudaGetSymbolAddress(&qkv_ptr, g_qkv);
    cudaGetSymbolAddress(&att_ptr, g_att);
    cudaGetSymbolAddress(&wfp, g_wfrag);

    cudaFuncSetAttribute(attn_hmma_kernel,
                         cudaFuncAttributeMaxDynamicSharedMemorySize, ATTN_SMEM);

    // 1. prep: bias+mask combine (log2e-scaled) + W fragment image
    build_sbm_kernel<<<dim3((NN + 255) / 256, NWIN * HEADS), 256>>>(bias_table, rel_index, mask);
    split_w_kernel<<<64, 256>>>(qkv_w, proj_w);
    // 2. QKV projection (3 N-tiles)
    gemm_hmma<3><<<MTOT / 64, 256>>>(x, (const uint4*)wfp, qkv_b, (float*)qkv_ptr);
    // 3. attention
    attn_hmma_kernel<<<dim3(BATCH, HEADS), 256, ATTN_SMEM>>>();
    // 4. output projection (tile 3 of the fragment image)
    gemm_hmma<1><<<MTOT / 64, 256>>>(
        (const float*)att_ptr, (const uint4*)wfp + 12288, proj_b, out);
}

// round 15
// speedup vs baseline: 1.2529x; 1.1121x over previous
#include <cuda_runtime.h>
#include <cuda_bf16.h>
#include <stdint.h>
#include <math.h>

#define BATCH 2048
#define NTOK 98
#define DIM 128
#define HEADS 4
#define NWIN 256
#define NN (NTOK * NTOK)   // 9604
#define MTOT (BATCH * NTOK)  // 200704

// Scratch (device globals)
__device__ float g_qkv[(size_t)MTOT * 384];                 // [m][s*128+h*32+d]
__device__ float g_att[(size_t)MTOT * 128];                 // [m][h*32+d]
__device__ uint32_t g_sbm[(size_t)NWIN * HEADS * 13 * 512]; // bias+mask, C-frag layout
__device__ uint4 g_wfrag[16384];                            // W in MMA-fragment layout

// ===========================================================================
__device__ __forceinline__ uint32_t smem_u32(const void* p) {
    uint32_t a;
    asm("{ .reg .u64 t; cvta.to.shared.u64 t, %1; cvt.u32.u64 %0, t; }" : "=r"(a) : "l"(p));
    return a;
}
__device__ __forceinline__ void ldsm_x4(uint32_t* r, uint32_t addr) {
    asm volatile("ldmatrix.sync.aligned.m8n8.x4.shared.b16 {%0,%1,%2,%3}, [%4];"
                 : "=r"(r[0]), "=r"(r[1]), "=r"(r[2]), "=r"(r[3]) : "r"(addr));
}
__device__ __forceinline__ void ldsm_x2(uint32_t* r, uint32_t addr) {
    asm volatile("ldmatrix.sync.aligned.m8n8.x2.shared.b16 {%0,%1}, [%2];"
                 : "=r"(r[0]), "=r"(r[1]) : "r"(addr));
}
__device__ __forceinline__ void ldsm_x4t(uint32_t* r, uint32_t addr) {
    asm volatile("ldmatrix.sync.aligned.m8n8.x4.trans.shared.b16 {%0,%1,%2,%3}, [%4];"
                 : "=r"(r[0]), "=r"(r[1]), "=r"(r[2]), "=r"(r[3]) : "r"(addr));
}
__device__ __forceinline__ void mma_bf16(float* d, const uint32_t* a, const uint32_t* b) {
    asm volatile("mma.sync.aligned.m16n8k16.row.col.f32.bf16.bf16.f32 "
                 "{%0,%1,%2,%3}, {%4,%5,%6,%7}, {%8,%9}, {%0,%1,%2,%3};"
                 : "+f"(d[0]), "+f"(d[1]), "+f"(d[2]), "+f"(d[3])
                 : "r"(a[0]), "r"(a[1]), "r"(a[2]), "r"(a[3]), "r"(b[0]), "r"(b[1]));
}
__device__ __forceinline__ float ex2f(float x) {
    float y;
    asm("ex2.approx.ftz.f32 %0, %1;" : "=f"(y) : "f"(x));
    return y;
}
__device__ __forceinline__ uint32_t packbf(float a, float b) {
    __nv_bfloat162 t = __float22bfloat162_rn(make_float2(a, b));
    return *(uint32_t*)&t;
}
__device__ __forceinline__ float lopart(float v) {
    return v - __bfloat162float(__float2bfloat16(v));
}
__device__ __forceinline__ void split4(float4 v, uint2& hi, uint2& lo) {
    __nv_bfloat16 hx = __float2bfloat16(v.x), hy = __float2bfloat16(v.y);
    __nv_bfloat16 hz = __float2bfloat16(v.z), hw = __float2bfloat16(v.w);
    __nv_bfloat162 h0 = __halves2bfloat162(hx, hy), h1 = __halves2bfloat162(hz, hw);
    hi.x = *(uint32_t*)&h0; hi.y = *(uint32_t*)&h1;
    lo.x = packbf(v.x - __bfloat162float(hx), v.y - __bfloat162float(hy));
    lo.y = packbf(v.z - __bfloat162float(hz), v.w - __bfloat162float(hw));
}
// truncation split of a float pair into hi (PRMT) and lo (residual)
__device__ __forceinline__ void tsplit2(float v0, float v1, uint32_t& hi, uint32_t& lo) {
    uint32_t b0 = __float_as_uint(v0), b1 = __float_as_uint(v1);
    hi = __byte_perm(b0, b1, 0x7632);
    float h0 = __uint_as_float(b0 & 0xFFFF0000u);
    float h1 = __uint_as_float(b1 & 0xFFFF0000u);
    lo = packbf(v0 - h0, v1 - h1);
}
// swizzled smem address: 256B-pitch rows, XOR 16B-chunk by row&7
__device__ __forceinline__ uint32_t swz(uint32_t r, uint32_t cb) {
    return (r << 8) + (cb ^ ((r & 7) << 4));
}

#define LOG2E 1.4426950408889634f

// ===========================================================================
// bias+mask combine, C-fragment layout:
//   g_sbm[wh][nt][row 0..127][l4] = bf16x2{(bias+mask)(row, nt*8+l4*2 .. +1)}*log2e
//   pads (row>=98 or col>=98) = -1e30
// ===========================================================================
__global__ void build_sbm_kernel(const float* __restrict__ table,
                                 const int* __restrict__ rel,
                                 const float* __restrict__ mask) {
    int rem = blockIdx.x * 256 + threadIdx.x;   // 0..6655 (13*512)
    int wh = blockIdx.y;
    if (rem >= 13 * 512) return;
    int nt = rem >> 9;
    int sub = rem & 511;
    int row = sub >> 2;
    int l4 = sub & 3;
    int w = wh >> 2, h = wh & 3;
    int col0 = nt * 8 + l4 * 2;
    float v0 = -1e30f, v1 = -1e30f;
    if (row < NTOK) {
        const float* mrow = mask + (size_t)w * NN + row * NTOK;
        const int* rrow = rel + row * NTOK;
        if (col0 < NTOK)
            v0 = (table[rrow[col0] * HEADS + h] + mrow[col0]) * LOG2E;
        if (col0 + 1 < NTOK)
            v1 = (table[rrow[col0 + 1] * HEADS + h] + mrow[col0 + 1]) * LOG2E;
    }
    g_sbm[((size_t)wh * 13 + nt) * 512 + sub] = packbf(v0, v1);
}

// ===========================================================================
// W pre-split into MMA B-fragment layout.
// ===========================================================================
__global__ void split_w_kernel(const float* __restrict__ qkv_w,
                               const float* __restrict__ proj_w) {
    int idx = blockIdx.x * 256 + threadIdx.x;   // 16384
    int tile = idx >> 12;
    int rem = idx & 4095;
    int lane = rem & 31;
    int nblk = (rem >> 5) & 15;
    int kc = rem >> 9;
    int n = nblk * 8 + (lane >> 2);
    int k0 = kc * 16 + (lane & 3) * 2;
    const float* W = (tile < 3) ? qkv_w + (size_t)(tile * 128 + n) * 128
                                : proj_w + (size_t)n * 128;
    float2 a = *(const float2*)(W + k0);
    float2 b = *(const float2*)(W + k0 + 8);
    uint4 o;
    {
        __nv_bfloat162 h = __halves2bfloat162(__float2bfloat16(a.x), __float2bfloat16(a.y));
        o.x = *(uint32_t*)&h;
        __nv_bfloat162 h2 = __halves2bfloat162(__float2bfloat16(b.x), __float2bfloat16(b.y));
        o.y = *(uint32_t*)&h2;
    }
    o.z = packbf(lopart(a.x), lopart(a.y));
    o.w = packbf(lopart(b.x), lopart(b.y));
    g_wfrag[idx] = o;
}

// ===========================================================================
// HMMA GEMM (unchanged): 64M x NITER*128N, W frags from L2.
// ===========================================================================
template<int NITER>
__global__ __launch_bounds__(256, 3) void gemm_hmma(
    const float* __restrict__ Af, const uint4* __restrict__ Wfrag,
    const float* __restrict__ bias, float* __restrict__ Cf)
{
    __shared__ char sm[32768];
    const uint32_t smb = smem_u32(sm);
    const int tid = threadIdx.x;
    const int wid = tid >> 5, lane = tid & 31;
    const size_t m0 = (size_t)blockIdx.x * 64;
    const int N = NITER * 128;

#pragma unroll
    for (int i = 0; i < 8; i++) {
        int idx = tid + 256 * i;
        int r = idx >> 5;
        int c4 = (idx & 31) << 2;
        float4 v = *(const float4*)(Af + (m0 + r) * 128 + c4);
        uint2 hi, lo;
        split4(v, hi, lo);
        *(uint2*)(sm + swz(r, c4 * 2)) = hi;
        *(uint2*)(sm + 16384 + swz(r, c4 * 2)) = lo;
    }
    __syncthreads();

    const int wm = (wid & 1) * 32;
    const int wnb = (wid >> 1) * 4;
    const int rq = lane >> 2, cq = (lane & 3) * 2;

#pragma unroll 1
    for (int it = 0; it < NITER; it++) {
        const int n0 = it * 128;

        float acc[2][4][4];
#pragma unroll
        for (int mi = 0; mi < 2; mi++)
#pragma unroll
            for (int ni = 0; ni < 4; ni++)
#pragma unroll
                for (int c = 0; c < 4; c++) acc[mi][ni][c] = 0.f;

#pragma unroll
        for (int kc = 0; kc < 8; kc++) {
            uint32_t cb = (uint32_t)(kc * 32 + ((lane >> 4) & 1) * 16);
            uint32_t ah[2][4], al[2][4];
#pragma unroll
            for (int mi = 0; mi < 2; mi++) {
                uint32_t r = (uint32_t)(wm + mi * 16 + (lane & 15));
                ldsm_x4(ah[mi], smb + swz(r, cb));
                ldsm_x4(al[mi], smb + 16384 + swz(r, cb));
            }
            const uint4* wp = Wfrag + ((size_t)(it * 8 + kc) * 16 + wnb) * 32 + lane;
#pragma unroll
            for (int ni = 0; ni < 4; ni++) {
                uint4 w = wp[ni * 32];
                uint32_t B0[2] = {w.x, w.y};
                uint32_t Bl[2] = {w.z, w.w};
#pragma unroll
                for (int mi = 0; mi < 2; mi++) {
                    mma_bf16(acc[mi][ni], ah[mi], B0);
                    mma_bf16(acc[mi][ni], al[mi], B0);
                    mma_bf16(acc[mi][ni], ah[mi], Bl);
                }
            }
        }

#pragma unroll
        for (int mi = 0; mi < 2; mi++) {
            size_t rA = m0 + wm + mi * 16 + rq;
            size_t rB = rA + 8;
#pragma unroll
            for (int ni = 0; ni < 4; ni++) {
                int col = n0 + wnb * 8 + ni * 8 + cq;
                float b0 = bias[col], b1 = bias[col + 1];
                *(float2*)(Cf + rA * N + col) =
                    make_float2(acc[mi][ni][0] + b0, acc[mi][ni][1] + b1);
                *(float2*)(Cf + rB * N + col) =
                    make_float2(acc[mi][ni][2] + b0, acc[mi][ni][3] + b1);
            }
        }
    }
}

// ===========================================================================
// HMMA attention: one CTA per (window, head), 256 threads (8 warps x 16 rows).
// No-max exp2 softmax; bias loads coalesced via C-fragment-layout g_sbm;
// branch-free softmax loop.
// ===========================================================================
#define PITCH 80
#define QH_OFF 0
#define QL_OFF 10240
#define KH_OFF 20480
#define KL_OFF 29440
#define VH_OFF 38400
#define VL_OFF 47360
#define ATTN_SMEM 56320

__global__ __launch_bounds__(256, 3) void attn_hmma_kernel() {
    extern __shared__ char smraw[];
    const uint32_t smb = smem_u32(smraw);
    char* sm = smraw;

    const int b = blockIdx.x, h = blockIdx.y;
    const int tid = threadIdx.x;
    const int wid = tid >> 5, lane = tid & 31;

    // ---- zero only pad rows (98..111) of all 6 tiles ----
    {
        uint4 z = make_uint4(0, 0, 0, 0);
        for (int idx = tid; idx < 420; idx += 256) {
            int t = idx / 70;
            int rem = idx - t * 70;
            int row = 98 + rem / 5;
            int ch = rem % 5;
            uint32_t base = (t < 2) ? (uint32_t)(t * 10240)
                                    : (uint32_t)(20480 + (t - 2) * 8960);
            *(uint4*)(sm + base + row * PITCH + ch * 16) = z;
        }
    }
    __syncthreads();

    // ---- load Q (scaled by scale*log2e) / K / V, split hi/lo ----
    const float qscale = 0.17677669529663687f * LOG2E;
    const float* qg = g_qkv + ((size_t)b * NTOK) * 384 + h * 32;
    for (int idx = tid; idx < NTOK * 4; idx += 256) {
        int n = idx >> 2, c8 = (idx & 3) << 3;
        const float* src = qg + (size_t)n * 384 + c8;
        uint32_t off = (uint32_t)(n * PITCH + c8 * 2);
        uint2 h0, l0, h1, l1;

        float4 qa = *(const float4*)src;
        float4 qb = *(const float4*)(src + 4);
        qa.x *= qscale; qa.y *= qscale; qa.z *= qscale; qa.w *= qscale;
        qb.x *= qscale; qb.y *= qscale; qb.z *= qscale; qb.w *= qscale;
        split4(qa, h0, l0); split4(qb, h1, l1);
        *(uint4*)(sm + QH_OFF + off) = make_uint4(h0.x, h0.y, h1.x, h1.y);
        *(uint4*)(sm + QL_OFF + off) = make_uint4(l0.x, l0.y, l1.x, l1.y);

        split4(*(const float4*)(src + 128), h0, l0);
        split4(*(const float4*)(src + 132), h1, l1);
        *(uint4*)(sm + KH_OFF + off) = make_uint4(h0.x, h0.y, h1.x, h1.y);
        *(uint4*)(sm + KL_OFF + off) = make_uint4(l0.x, l0.y, l1.x, l1.y);

        split4(*(const float4*)(src + 256), h0, l0);
        split4(*(const float4*)(src + 260), h1, l1);
        *(uint4*)(sm + VH_OFF + off) = make_uint4(h0.x, h0.y, h1.x, h1.y);
        *(uint4*)(sm + VL_OFF + off) = make_uint4(l0.x, l0.y, l1.x, l1.y);
    }
    __syncthreads();

    if (wid == 7) return;   // rows 112..127 are pure padding

    const int l8 = lane & 7;
    const int rq = lane >> 2;
    const int cq = (lane & 3) * 2;
    const int l4 = lane & 3;
    const int sel16 = (lane >> 4) & 1;

    // ---- S = QK^T: single kc loop, 3 products share fragments ----
    float acc[13][4];
#pragma unroll
    for (int nt = 0; nt < 13; nt++)
#pragma unroll
        for (int c = 0; c < 4; c++) acc[nt][c] = 0.f;

#pragma unroll
    for (int kc = 0; kc < 2; kc++) {
        uint32_t r = (uint32_t)(wid * 16 + (lane & 15));
        uint32_t aoff = (uint32_t)(kc * 32 + sel16 * 16);
        uint32_t qh[4], ql[4];
        ldsm_x4(qh, smb + QH_OFF + r * PITCH + aoff);
        ldsm_x4(ql, smb + QL_OFF + r * PITCH + aoff);
        uint32_t boff = (uint32_t)(kc * 32 + ((lane >> 3) & 1) * 16);
#pragma unroll
        for (int nt2 = 0; nt2 < 6; nt2++) {
            uint32_t row = (uint32_t)((2 * nt2 + sel16) * 8 + l8);
            uint32_t kh[4], kl[4];
            ldsm_x4(kh, smb + KH_OFF + row * PITCH + boff);
            ldsm_x4(kl, smb + KL_OFF + row * PITCH + boff);
            mma_bf16(acc[2 * nt2], qh, kh);
            mma_bf16(acc[2 * nt2], qh, kl);
            mma_bf16(acc[2 * nt2], ql, kh);
            mma_bf16(acc[2 * nt2 + 1], qh, kh + 2);
            mma_bf16(acc[2 * nt2 + 1], qh, kl + 2);
            mma_bf16(acc[2 * nt2 + 1], ql, kh + 2);
        }
        {
            uint32_t kh[2], kl[2];
            ldsm_x2(kh, smb + KH_OFF + (uint32_t)(96 + l8) * PITCH + boff);
            ldsm_x2(kl, smb + KL_OFF + (uint32_t)(96 + l8) * PITCH + boff);
            mma_bf16(acc[12], qh, kh);
            mma_bf16(acc[12], qh, kl);
            mma_bf16(acc[12], ql, kh);
        }
    }

    // ---- fused bias + exp2 + rowsum (branch-free, coalesced sbm) ----
    const uint32_t* sbm = g_sbm +
        ((size_t)((b & (NWIN - 1)) * HEADS + h)) * (13 * 512);
    const int rA = wid * 16 + rq;
    const int rB = rA + 8;
    const uint32_t sboffA = (uint32_t)(rA * 4 + l4);
    float sA = 0.f, sB = 0.f;
#pragma unroll
    for (int nt = 0; nt < 13; nt++) {
        uint32_t uA = __ldg(sbm + nt * 512 + sboffA);
        uint32_t uB = __ldg(sbm + nt * 512 + sboffA + 32);
        __nv_bfloat162 bA = *(__nv_bfloat162*)&uA;
        __nv_bfloat162 bB = *(__nv_bfloat162*)&uB;
        float e0 = ex2f(acc[nt][0] + __bfloat162float(bA.x));
        float e1 = ex2f(acc[nt][1] + __bfloat162float(bA.y));
        float e2 = ex2f(acc[nt][2] + __bfloat162float(bB.x));
        float e3 = ex2f(acc[nt][3] + __bfloat162float(bB.y));
        acc[nt][0] = e0; acc[nt][1] = e1;
        acc[nt][2] = e2; acc[nt][3] = e3;
        sA += e0 + e1; sB += e2 + e3;
    }
    sA += __shfl_xor_sync(0xffffffffu, sA, 1);
    sA += __shfl_xor_sync(0xffffffffu, sA, 2);
    sB += __shfl_xor_sync(0xffffffffu, sB, 1);
    sB += __shfl_xor_sync(0xffffffffu, sB, 2);

    // ---- O = P V: single kc loop, 3 products share V fragments ----
    float oacc[4][4];
#pragma unroll
    for (int nh = 0; nh < 4; nh++)
#pragma unroll
        for (int c = 0; c < 4; c++) oacc[nh][c] = 0.f;

#pragma unroll
    for (int kc = 0; kc < 7; kc++) {
        int nt0 = 2 * kc, nt1 = nt0 + 1;
        float w0 = 0.f, w1 = 0.f, w2 = 0.f, w3 = 0.f;
        if (nt1 < 13) {
            w0 = acc[nt1][0]; w1 = acc[nt1][1];
            w2 = acc[nt1][2]; w3 = acc[nt1][3];
        }
        uint32_t amh[4], aml[4];
        tsplit2(acc[nt0][0], acc[nt0][1], amh[0], aml[0]);
        tsplit2(acc[nt0][2], acc[nt0][3], amh[1], aml[1]);
        tsplit2(w0, w1, amh[2], aml[2]);
        tsplit2(w2, w3, amh[3], aml[3]);
        uint32_t vrow = (uint32_t)(kc * 16 + ((lane >> 3) & 1) * 8 + l8);
#pragma unroll
        for (int nh2 = 0; nh2 < 2; nh2++) {
            uint32_t coff = (uint32_t)((2 * nh2 + sel16) * 16);
            uint32_t vh[4], vl[4];
            ldsm_x4t(vh, smb + VH_OFF + vrow * PITCH + coff);
            ldsm_x4t(vl, smb + VL_OFF + vrow * PITCH + coff);
            mma_bf16(oacc[2 * nh2], amh, vh);
            mma_bf16(oacc[2 * nh2], amh, vl);
            mma_bf16(oacc[2 * nh2], aml, vh);
            mma_bf16(oacc[2 * nh2 + 1], amh, vh + 2);
            mma_bf16(oacc[2 * nh2 + 1], amh, vl + 2);
            mma_bf16(oacc[2 * nh2 + 1], aml, vh + 2);
        }
    }

    // ---- epilogue ----
    float invA = 1.0f / sA;
    float invB = 1.0f / sB;
#pragma unroll
    for (int nh = 0; nh < 4; nh++) {
        int col = nh * 8 + cq;
        if (rA < 98) {
            float2 o = make_float2(oacc[nh][0] * invA, oacc[nh][1] * invA);
            *(float2*)(g_att + ((size_t)b * NTOK + rA) * 128 + h * 32 + col) = o;
        }
        if (rB < 98) {
            float2 o = make_float2(oacc[nh][2] * invB, oacc[nh][3] * invB);
            *(float2*)(g_att + ((size_t)b * NTOK + rB) * 128 + h * 32 + col) = o;
        }
    }
}

// ===========================================================================
extern "C" void kernel_launch(void* const* d_in, const int* in_sizes, int n_in,
                              void* d_out, int out_size) {
    const float* x          = (const float*)d_in[0];
    const float* mask       = (const float*)d_in[1];
    const float* qkv_w      = (const float*)d_in[2];
    const float* qkv_b      = (const float*)d_in[3];
    const float* proj_w     = (const float*)d_in[4];
    const float* proj_b     = (const float*)d_in[5];
    const float* bias_table = (const float*)d_in[6];
    const int*   rel_index  = (const int*)d_in[7];
    float* out = (float*)d_out;

    void *qkv_ptr, *att_ptr, *wfp;
    cudaGetSymbolAddress(&qkv_ptr, g_qkv);
    cudaGetSymbolAddress(&att_ptr, g_att);
    cudaGetSymbolAddress(&wfp, g_wfrag);

    cudaFuncSetAttribute(attn_hmma_kernel,
                         cudaFuncAttributeMaxDynamicSharedMemorySize, ATTN_SMEM);

    // 1. prep: bias+mask combine (fragment layout) + W fragment image
    build_sbm_kernel<<<dim3(26, NWIN * HEADS), 256>>>(bias_table, rel_index, mask);
    split_w_kernel<<<64, 256>>>(qkv_w, proj_w);
    // 2. QKV projection (3 N-tiles)
    gemm_hmma<3><<<MTOT / 64, 256>>>(x, (const uint4*)wfp, qkv_b, (float*)qkv_ptr);
    // 3. attention
    attn_hmma_kernel<<<dim3(BATCH, HEADS), 256, ATTN_SMEM>>>();
    // 4. output projection (tile 3 of the fragment image)
    gemm_hmma<1><<<MTOT / 64, 256>>>(
        (const float*)att_ptr, (const uint4*)wfp + 12288, proj_b, out);
}

// round 16
// speedup vs baseline: 1.2869x; 1.0272x over previous
#include <cuda_runtime.h>
#include <cuda_bf16.h>
#include <stdint.h>
#include <math.h>

#define BATCH 2048
#define NTOK 98
#define DIM 128
#define HEADS 4
#define NWIN 256
#define NN (NTOK * NTOK)   // 9604
#define MTOT (BATCH * NTOK)  // 200704

// Scratch (device globals)
// packed element: uint32 = {bf16 hi | bf16 lo(residual)}  (hi in high 16 bits)
__device__ uint32_t g_qkv[(size_t)MTOT * 384];              // packed qkv
__device__ uint32_t g_att[(size_t)MTOT * 128];              // packed attn out
__device__ uint32_t g_sbm[(size_t)NWIN * HEADS * 13 * 512]; // bias+mask, C-frag layout
__device__ uint4 g_wfrag[16384];                            // W in MMA-fragment layout
__device__ float g_qkvb[384];                               // qkv bias (Q slice pre-scaled)

#define LOG2E 1.4426950408889634f
#define QSCALE (0.17677669529663687f * LOG2E)

// ===========================================================================
__device__ __forceinline__ uint32_t smem_u32(const void* p) {
    uint32_t a;
    asm("{ .reg .u64 t; cvta.to.shared.u64 t, %1; cvt.u32.u64 %0, t; }" : "=r"(a) : "l"(p));
    return a;
}
__device__ __forceinline__ void ldsm_x4(uint32_t* r, uint32_t addr) {
    asm volatile("ldmatrix.sync.aligned.m8n8.x4.shared.b16 {%0,%1,%2,%3}, [%4];"
                 : "=r"(r[0]), "=r"(r[1]), "=r"(r[2]), "=r"(r[3]) : "r"(addr));
}
__device__ __forceinline__ void ldsm_x2(uint32_t* r, uint32_t addr) {
    asm volatile("ldmatrix.sync.aligned.m8n8.x2.shared.b16 {%0,%1}, [%2];"
                 : "=r"(r[0]), "=r"(r[1]) : "r"(addr));
}
__device__ __forceinline__ void ldsm_x4t(uint32_t* r, uint32_t addr) {
    asm volatile("ldmatrix.sync.aligned.m8n8.x4.trans.shared.b16 {%0,%1,%2,%3}, [%4];"
                 : "=r"(r[0]), "=r"(r[1]), "=r"(r[2]), "=r"(r[3]) : "r"(addr));
}
__device__ __forceinline__ void mma_bf16(float* d, const uint32_t* a, const uint32_t* b) {
    asm volatile("mma.sync.aligned.m16n8k16.row.col.f32.bf16.bf16.f32 "
                 "{%0,%1,%2,%3}, {%4,%5,%6,%7}, {%8,%9}, {%0,%1,%2,%3};"
                 : "+f"(d[0]), "+f"(d[1]), "+f"(d[2]), "+f"(d[3])
                 : "r"(a[0]), "r"(a[1]), "r"(a[2]), "r"(a[3]), "r"(b[0]), "r"(b[1]));
}
__device__ __forceinline__ float ex2f(float x) {
    float y;
    asm("ex2.approx.ftz.f32 %0, %1;" : "=f"(y) : "f"(x));
    return y;
}
__device__ __forceinline__ uint32_t packbf(float a, float b) {
    __nv_bfloat162 t = __float22bfloat162_rn(make_float2(a, b));
    return *(uint32_t*)&t;
}
__device__ __forceinline__ float lopart(float v) {
    return v - __bfloat162float(__float2bfloat16(v));
}
// packed element: {hi16 (trunc) | lo16 (rn residual)}
__device__ __forceinline__ uint32_t pack_e(float v) {
    uint32_t hb = __float_as_uint(v) & 0xFFFF0000u;
    float l = v - __uint_as_float(hb);
    __nv_bfloat16 lb = __float2bfloat16(l);
    return hb | (uint32_t)(*(uint16_t*)&lb);
}
// hi pair / lo pair from two packed elements
#define HIPAIR(a, b) __byte_perm((a), (b), 0x7632)
#define LOPAIR(a, b) __byte_perm((a), (b), 0x5410)
// truncation split of a float pair into hi (PRMT) and lo (residual)
__device__ __forceinline__ void tsplit2(float v0, float v1, uint32_t& hi, uint32_t& lo) {
    uint32_t b0 = __float_as_uint(v0), b1 = __float_as_uint(v1);
    hi = __byte_perm(b0, b1, 0x7632);
    float h0 = __uint_as_float(b0 & 0xFFFF0000u);
    float h1 = __uint_as_float(b1 & 0xFFFF0000u);
    lo = packbf(v0 - h0, v1 - h1);
}
__device__ __forceinline__ void split4(float4 v, uint2& hi, uint2& lo) {
    __nv_bfloat16 hx = __float2bfloat16(v.x), hy = __float2bfloat16(v.y);
    __nv_bfloat16 hz = __float2bfloat16(v.z), hw = __float2bfloat16(v.w);
    __nv_bfloat162 h0 = __halves2bfloat162(hx, hy), h1 = __halves2bfloat162(hz, hw);
    hi.x = *(uint32_t*)&h0; hi.y = *(uint32_t*)&h1;
    lo.x = packbf(v.x - __bfloat162float(hx), v.y - __bfloat162float(hy));
    lo.y = packbf(v.z - __bfloat162float(hz), v.w - __bfloat162float(hw));
}
// swizzled smem address: 256B-pitch rows, XOR 16B-chunk by row&7
__device__ __forceinline__ uint32_t swz(uint32_t r, uint32_t cb) {
    return (r << 8) + (cb ^ ((r & 7) << 4));
}

// ===========================================================================
// prep kernels
// ===========================================================================
__global__ void build_sbm_kernel(const float* __restrict__ table,
                                 const int* __restrict__ rel,
                                 const float* __restrict__ mask) {
    int rem = blockIdx.x * 256 + threadIdx.x;   // 0..6655 (13*512)
    int wh = blockIdx.y;
    if (rem >= 13 * 512) return;
    int nt = rem >> 9;
    int sub = rem & 511;
    int row = sub >> 2;
    int l4 = sub & 3;
    int w = wh >> 2, h = wh & 3;
    int col0 = nt * 8 + l4 * 2;
    float v0 = -1e30f, v1 = -1e30f;
    if (row < NTOK) {
        const float* mrow = mask + (size_t)w * NN + row * NTOK;
        const int* rrow = rel + row * NTOK;
        if (col0 < NTOK)
            v0 = (table[rrow[col0] * HEADS + h] + mrow[col0]) * LOG2E;
        if (col0 + 1 < NTOK)
            v1 = (table[rrow[col0 + 1] * HEADS + h] + mrow[col0 + 1]) * LOG2E;
    }
    g_sbm[((size_t)wh * 13 + nt) * 512 + sub] = packbf(v0, v1);
}

// W pre-split into MMA B-fragment layout; Q slice (tile 0) pre-scaled.
// Also scales qkv bias into g_qkvb.
__global__ void split_w_kernel(const float* __restrict__ qkv_w,
                               const float* __restrict__ proj_w,
                               const float* __restrict__ qkv_b) {
    int idx = blockIdx.x * 256 + threadIdx.x;   // 16384
    if (idx < 384)
        g_qkvb[idx] = qkv_b[idx] * ((idx < 128) ? QSCALE : 1.0f);
    int tile = idx >> 12;
    int rem = idx & 4095;
    int lane = rem & 31;
    int nblk = (rem >> 5) & 15;
    int kc = rem >> 9;
    int n = nblk * 8 + (lane >> 2);
    int k0 = kc * 16 + (lane & 3) * 2;
    const float* W = (tile < 3) ? qkv_w + (size_t)(tile * 128 + n) * 128
                                : proj_w + (size_t)n * 128;
    float2 a = *(const float2*)(W + k0);
    float2 b = *(const float2*)(W + k0 + 8);
    float s = (tile == 0) ? QSCALE : 1.0f;
    a.x *= s; a.y *= s; b.x *= s; b.y *= s;
    uint4 o;
    {
        __nv_bfloat162 h = __halves2bfloat162(__float2bfloat16(a.x), __float2bfloat16(a.y));
        o.x = *(uint32_t*)&h;
        __nv_bfloat162 h2 = __halves2bfloat162(__float2bfloat16(b.x), __float2bfloat16(b.y));
        o.y = *(uint32_t*)&h2;
    }
    o.z = packbf(lopart(a.x), lopart(a.y));
    o.w = packbf(lopart(b.x), lopart(b.y));
    g_wfrag[idx] = o;
}

// ===========================================================================
// HMMA GEMM: 64M x NITER*128N, W frags from L2.
// PIN: A is packed uint32 elements (PRMT unpack); else fp32 (split inline).
// POUT: write packed elements; else fp32.
// ===========================================================================
template<int NITER, int PIN, int POUT>
__global__ __launch_bounds__(256, 3) void gemm_hmma(
    const void* __restrict__ Ain, const uint4* __restrict__ Wfrag,
    const float* __restrict__ bias, void* __restrict__ Cout)
{
    __shared__ char sm[32768];
    const uint32_t smb = smem_u32(sm);
    const int tid = threadIdx.x;
    const int wid = tid >> 5, lane = tid & 31;
    const size_t m0 = (size_t)blockIdx.x * 64;
    const int N = NITER * 128;

#pragma unroll
    for (int i = 0; i < 8; i++) {
        int idx = tid + 256 * i;
        int r = idx >> 5;
        int c4 = (idx & 31) << 2;
        uint2 hi, lo;
        if (PIN) {
            uint4 p = ((const uint4*)Ain)[(m0 + r) * 32 + (c4 >> 2)];
            hi.x = HIPAIR(p.x, p.y); hi.y = HIPAIR(p.z, p.w);
            lo.x = LOPAIR(p.x, p.y); lo.y = LOPAIR(p.z, p.w);
        } else {
            float4 v = *(const float4*)((const float*)Ain + (m0 + r) * 128 + c4);
            split4(v, hi, lo);
        }
        *(uint2*)(sm + swz(r, c4 * 2)) = hi;
        *(uint2*)(sm + 16384 + swz(r, c4 * 2)) = lo;
    }
    __syncthreads();

    const int wm = (wid & 1) * 32;
    const int wnb = (wid >> 1) * 4;
    const int rq = lane >> 2, cq = (lane & 3) * 2;

#pragma unroll 1
    for (int it = 0; it < NITER; it++) {
        const int n0 = it * 128;

        float acc[2][4][4];
#pragma unroll
        for (int mi = 0; mi < 2; mi++)
#pragma unroll
            for (int ni = 0; ni < 4; ni++)
#pragma unroll
                for (int c = 0; c < 4; c++) acc[mi][ni][c] = 0.f;

#pragma unroll
        for (int kc = 0; kc < 8; kc++) {
            uint32_t cb = (uint32_t)(kc * 32 + ((lane >> 4) & 1) * 16);
            uint32_t ah[2][4], al[2][4];
#pragma unroll
            for (int mi = 0; mi < 2; mi++) {
                uint32_t r = (uint32_t)(wm + mi * 16 + (lane & 15));
                ldsm_x4(ah[mi], smb + swz(r, cb));
                ldsm_x4(al[mi], smb + 16384 + swz(r, cb));
            }
            const uint4* wp = Wfrag + ((size_t)(it * 8 + kc) * 16 + wnb) * 32 + lane;
#pragma unroll
            for (int ni = 0; ni < 4; ni++) {
                uint4 w = wp[ni * 32];
                uint32_t B0[2] = {w.x, w.y};
                uint32_t Bl[2] = {w.z, w.w};
#pragma unroll
                for (int mi = 0; mi < 2; mi++) {
                    mma_bf16(acc[mi][ni], ah[mi], B0);
                    mma_bf16(acc[mi][ni], al[mi], B0);
                    mma_bf16(acc[mi][ni], ah[mi], Bl);
                }
            }
        }

#pragma unroll
        for (int mi = 0; mi < 2; mi++) {
            size_t rA = m0 + wm + mi * 16 + rq;
            size_t rB = rA + 8;
#pragma unroll
            for (int ni = 0; ni < 4; ni++) {
                int col = n0 + wnb * 8 + ni * 8 + cq;
                float b0 = bias[col], b1 = bias[col + 1];
                float v0 = acc[mi][ni][0] + b0, v1 = acc[mi][ni][1] + b1;
                float v2 = acc[mi][ni][2] + b0, v3 = acc[mi][ni][3] + b1;
                if (POUT) {
                    *(uint2*)((uint32_t*)Cout + rA * N + col) =
                        make_uint2(pack_e(v0), pack_e(v1));
                    *(uint2*)((uint32_t*)Cout + rB * N + col) =
                        make_uint2(pack_e(v2), pack_e(v3));
                } else {
                    *(float2*)((float*)Cout + rA * N + col) = make_float2(v0, v1);
                    *(float2*)((float*)Cout + rB * N + col) = make_float2(v2, v3);
                }
            }
        }
    }
}

// ===========================================================================
// HMMA attention: one CTA per (window, head), 256 threads (8 warps x 16 rows).
// Packed qkv in (pure-PRMT prologue; scale pre-folded), packed O out.
// ===========================================================================
#define PITCH 80
#define QH_OFF 0
#define QL_OFF 10240
#define KH_OFF 20480
#define KL_OFF 29440
#define VH_OFF 38400
#define VL_OFF 47360
#define ATTN_SMEM 56320

__global__ __launch_bounds__(256, 3) void attn_hmma_kernel() {
    extern __shared__ char smraw[];
    const uint32_t smb = smem_u32(smraw);
    char* sm = smraw;

    const int b = blockIdx.x, h = blockIdx.y;
    const int tid = threadIdx.x;
    const int wid = tid >> 5, lane = tid & 31;

    // ---- zero only pad rows (98..111) of all 6 tiles ----
    {
        uint4 z = make_uint4(0, 0, 0, 0);
        for (int idx = tid; idx < 420; idx += 256) {
            int t = idx / 70;
            int rem = idx - t * 70;
            int row = 98 + rem / 5;
            int ch = rem % 5;
            uint32_t base = (t < 2) ? (uint32_t)(t * 10240)
                                    : (uint32_t)(20480 + (t - 2) * 8960);
            *(uint4*)(sm + base + row * PITCH + ch * 16) = z;
        }
    }
    __syncthreads();

    // ---- unpack Q/K/V packed planes into hi/lo tiles (pure PRMT) ----
    const uint32_t* qg = g_qkv + ((size_t)b * NTOK) * 384 + h * 32;
    for (int idx = tid; idx < NTOK * 4; idx += 256) {
        int n = idx >> 2, c8 = (idx & 3) << 3;
        const uint32_t* src = qg + (size_t)n * 384 + c8;
        uint32_t off = (uint32_t)(n * PITCH + c8 * 2);

        uint4 a = *(const uint4*)src;
        uint4 c = *(const uint4*)(src + 4);
        *(uint4*)(sm + QH_OFF + off) =
            make_uint4(HIPAIR(a.x, a.y), HIPAIR(a.z, a.w), HIPAIR(c.x, c.y), HIPAIR(c.z, c.w));
        *(uint4*)(sm + QL_OFF + off) =
            make_uint4(LOPAIR(a.x, a.y), LOPAIR(a.z, a.w), LOPAIR(c.x, c.y), LOPAIR(c.z, c.w));

        a = *(const uint4*)(src + 128);
        c = *(const uint4*)(src + 132);
        *(uint4*)(sm + KH_OFF + off) =
            make_uint4(HIPAIR(a.x, a.y), HIPAIR(a.z, a.w), HIPAIR(c.x, c.y), HIPAIR(c.z, c.w));
        *(uint4*)(sm + KL_OFF + off) =
            make_uint4(LOPAIR(a.x, a.y), LOPAIR(a.z, a.w), LOPAIR(c.x, c.y), LOPAIR(c.z, c.w));

        a = *(const uint4*)(src + 256);
        c = *(const uint4*)(src + 260);
        *(uint4*)(sm + VH_OFF + off) =
            make_uint4(HIPAIR(a.x, a.y), HIPAIR(a.z, a.w), HIPAIR(c.x, c.y), HIPAIR(c.z, c.w));
        *(uint4*)(sm + VL_OFF + off) =
            make_uint4(LOPAIR(a.x, a.y), LOPAIR(a.z, a.w), LOPAIR(c.x, c.y), LOPAIR(c.z, c.w));
    }
    __syncthreads();

    if (wid == 7) return;   // rows 112..127 are pure padding

    const int l8 = lane & 7;
    const int rq = lane >> 2;
    const int cq = (lane & 3) * 2;
    const int l4 = lane & 3;
    const int sel16 = (lane >> 4) & 1;

    // ---- S = QK^T: single kc loop, 3 products share fragments ----
    float acc[13][4];
#pragma unroll
    for (int nt = 0; nt < 13; nt++)
#pragma unroll
        for (int c = 0; c < 4; c++) acc[nt][c] = 0.f;

#pragma unroll
    for (int kc = 0; kc < 2; kc++) {
        uint32_t r = (uint32_t)(wid * 16 + (lane & 15));
        uint32_t aoff = (uint32_t)(kc * 32 + sel16 * 16);
        uint32_t qh[4], ql[4];
        ldsm_x4(qh, smb + QH_OFF + r * PITCH + aoff);
        ldsm_x4(ql, smb + QL_OFF + r * PITCH + aoff);
        uint32_t boff = (uint32_t)(kc * 32 + ((lane >> 3) & 1) * 16);
#pragma unroll
        for (int nt2 = 0; nt2 < 6; nt2++) {
            uint32_t row = (uint32_t)((2 * nt2 + sel16) * 8 + l8);
            uint32_t kh[4], kl[4];
            ldsm_x4(kh, smb + KH_OFF + row * PITCH + boff);
            ldsm_x4(kl, smb + KL_OFF + row * PITCH + boff);
            mma_bf16(acc[2 * nt2], qh, kh);
            mma_bf16(acc[2 * nt2], qh, kl);
            mma_bf16(acc[2 * nt2], ql, kh);
            mma_bf16(acc[2 * nt2 + 1], qh, kh + 2);
            mma_bf16(acc[2 * nt2 + 1], qh, kl + 2);
            mma_bf16(acc[2 * nt2 + 1], ql, kh + 2);
        }
        {
            uint32_t kh[2], kl[2];
            ldsm_x2(kh, smb + KH_OFF + (uint32_t)(96 + l8) * PITCH + boff);
            ldsm_x2(kl, smb + KL_OFF + (uint32_t)(96 + l8) * PITCH + boff);
            mma_bf16(acc[12], qh, kh);
            mma_bf16(acc[12], qh, kl);
            mma_bf16(acc[12], ql, kh);
        }
    }

    // ---- fused bias + exp2 + rowsum (branch-free, coalesced sbm) ----
    const uint32_t* sbm = g_sbm +
        ((size_t)((b & (NWIN - 1)) * HEADS + h)) * (13 * 512);
    const int rA = wid * 16 + rq;
    const int rB = rA + 8;
    const uint32_t sboffA = (uint32_t)(rA * 4 + l4);
    float sA = 0.f, sB = 0.f;
#pragma unroll
    for (int nt = 0; nt < 13; nt++) {
        uint32_t uA = __ldg(sbm + nt * 512 + sboffA);
        uint32_t uB = __ldg(sbm + nt * 512 + sboffA + 32);
        __nv_bfloat162 bA = *(__nv_bfloat162*)&uA;
        __nv_bfloat162 bB = *(__nv_bfloat162*)&uB;
        float e0 = ex2f(acc[nt][0] + __bfloat162float(bA.x));
        float e1 = ex2f(acc[nt][1] + __bfloat162float(bA.y));
        float e2 = ex2f(acc[nt][2] + __bfloat162float(bB.x));
        float e3 = ex2f(acc[nt][3] + __bfloat162float(bB.y));
        acc[nt][0] = e0; acc[nt][1] = e1;
        acc[nt][2] = e2; acc[nt][3] = e3;
        sA += e0 + e1; sB += e2 + e3;
    }
    sA += __shfl_xor_sync(0xffffffffu, sA, 1);
    sA += __shfl_xor_sync(0xffffffffu, sA, 2);
    sB += __shfl_xor_sync(0xffffffffu, sB, 1);
    sB += __shfl_xor_sync(0xffffffffu, sB, 2);

    // ---- O = P V: single kc loop, 3 products share V fragments ----
    float oacc[4][4];
#pragma unroll
    for (int nh = 0; nh < 4; nh++)
#pragma unroll
        for (int c = 0; c < 4; c++) oacc[nh][c] = 0.f;

#pragma unroll
    for (int kc = 0; kc < 7; kc++) {
        int nt0 = 2 * kc, nt1 = nt0 + 1;
        float w0 = 0.f, w1 = 0.f, w2 = 0.f, w3 = 0.f;
        if (nt1 < 13) {
            w0 = acc[nt1][0]; w1 = acc[nt1][1];
            w2 = acc[nt1][2]; w3 = acc[nt1][3];
        }
        uint32_t amh[4], aml[4];
        tsplit2(acc[nt0][0], acc[nt0][1], amh[0], aml[0]);
        tsplit2(acc[nt0][2], acc[nt0][3], amh[1], aml[1]);
        tsplit2(w0, w1, amh[2], aml[2]);
        tsplit2(w2, w3, amh[3], aml[3]);
        uint32_t vrow = (uint32_t)(kc * 16 + ((lane >> 3) & 1) * 8 + l8);
#pragma unroll
        for (int nh2 = 0; nh2 < 2; nh2++) {
            uint32_t coff = (uint32_t)((2 * nh2 + sel16) * 16);
            uint32_t vh[4], vl[4];
            ldsm_x4t(vh, smb + VH_OFF + vrow * PITCH + coff);
            ldsm_x4t(vl, smb + VL_OFF + vrow * PITCH + coff);
            mma_bf16(oacc[2 * nh2], amh, vh);
            mma_bf16(oacc[2 * nh2], amh, vl);
            mma_bf16(oacc[2 * nh2], aml, vh);
            mma_bf16(oacc[2 * nh2 + 1], amh, vh + 2);
            mma_bf16(oacc[2 * nh2 + 1], amh, vl + 2);
            mma_bf16(oacc[2 * nh2 + 1], aml, vh + 2);
        }
    }

    // ---- epilogue: normalize + pack ----
    float invA = 1.0f / sA;
    float invB = 1.0f / sB;
#pragma unroll
    for (int nh = 0; nh < 4; nh++) {
        int col = nh * 8 + cq;
        if (rA < 98) {
            *(uint2*)(g_att + ((size_t)b * NTOK + rA) * 128 + h * 32 + col) =
                make_uint2(pack_e(oacc[nh][0] * invA), pack_e(oacc[nh][1] * invA));
        }
        if (rB < 98) {
            *(uint2*)(g_att + ((size_t)b * NTOK + rB) * 128 + h * 32 + col) =
                make_uint2(pack_e(oacc[nh][2] * invB), pack_e(oacc[nh][3] * invB));
        }
    }
}

// ===========================================================================
extern "C" void kernel_launch(void* const* d_in, const int* in_sizes, int n_in,
                              void* d_out, int out_size) {
    const float* x          = (const float*)d_in[0];
    const float* mask       = (const float*)d_in[1];
    const float* qkv_w      = (const float*)d_in[2];
    const float* qkv_b      = (const float*)d_in[3];
    const float* proj_w     = (const float*)d_in[4];
    const float* proj_b     = (const float*)d_in[5];
    const float* bias_table = (const float*)d_in[6];
    const int*   rel_index  = (const int*)d_in[7];
    float* out = (float*)d_out;

    void *qkv_ptr, *att_ptr, *wfp, *qbp;
    cudaGetSymbolAddress(&qkv_ptr, g_qkv);
    cudaGetSymbolAddress(&att_ptr, g_att);
    cudaGetSymbolAddress(&wfp, g_wfrag);
    cudaGetSymbolAddress(&qbp, g_qkvb);

    cudaFuncSetAttribute(attn_hmma_kernel,
                         cudaFuncAttributeMaxDynamicSharedMemorySize, ATTN_SMEM);

    // 1. prep: bias+mask combine (fragment layout) + W fragment image (+bias scale)
    build_sbm_kernel<<<dim3(26, NWIN * HEADS), 256>>>(bias_table, rel_index, mask);
    split_w_kernel<<<64, 256>>>(qkv_w, proj_w, qkv_b);
    // 2. QKV projection: fp32 in -> packed out (Q pre-scaled via W/bias)
    gemm_hmma<3, 0, 1><<<MTOT / 64, 256>>>(
        x, (const uint4*)wfp, (const float*)qbp, qkv_ptr);
    // 3. attention (packed in/out)
    attn_hmma_kernel<<<dim3(BATCH, HEADS), 256, ATTN_SMEM>>>();
    // 4. output projection: packed in -> fp32 out
    gemm_hmma<1, 1, 0><<<MTOT / 64, 256>>>(
        att_ptr, (const uint4*)wfp + 12288, proj_b, out);
}